// round 1
// baseline (speedup 1.0000x reference)
#include <cuda_runtime.h>
#include <math.h>
#include <stdint.h>

// Shapes
#define BB      64
#define CC      862
#define FBINS   257
#define DM      256
#define DFF     512
#define NL      3
#define EPSV    1e-5f

#define EMB_M   (BB*CC)          // 55168
#define MROWS   (2*BB*CC)        // 110336
#define NSTATB  256              // stats partial blocks
#define ROWS_PER_STATB (MROWS/NSTATB)  // 431

// ---------------- scratch (device globals; allocation-free) ----------------
__device__ float g_act[(size_t)MROWS * DM];   // activations (pre-norm), ping
__device__ float g_src[(size_t)MROWS * DM];   // src after attention residual
__device__ float g_ff [(size_t)MROWS * DFF];  // FF hidden
__device__ float g_psum[NSTATB * DM];
__device__ float g_psq [NSTATB * DM];
__device__ float g_al[DM];                    // current norm scale
__device__ float g_bt[DM];                    // current norm shift

// ---------------- init affine to identity ----------------
__global__ void k_init_affine() {
    int t = threadIdx.x;
    g_al[t] = 1.0f;
    g_bt[t] = 0.0f;
}

// ---------------- embedding GEMM ----------------
// which==0: y_re = x_re@Wre^T - x_im@Wim^T + bre   -> rows [0, 55168)
// which==1: y_im = x_re@Wim^T + x_im@Wre^T + bim   -> rows [55168, 110336)
// Virtual K = 514: k<257 pairs (x_re, W0), k>=257 pairs (x_im, sgn*W1)
__global__ __launch_bounds__(256) void k_embed_gemm(
    const float* __restrict__ xre, const float* __restrict__ xim,
    const float* __restrict__ Wre, const float* __restrict__ Wim,
    const float* __restrict__ bre, const float* __restrict__ bim,
    int which)
{
    __shared__ float As[8][128];
    __shared__ float Bs[8][128];
    const int tid = threadIdx.x;
    const int m0 = blockIdx.y * 128;
    const int n0 = blockIdx.x * 128;
    const int lr  = tid >> 1;         // row within tile, 0..127
    const int lk4 = (tid & 1) * 4;    // 0 or 4
    const int tm = (tid >> 4) * 8;
    const int tn = (tid & 15) * 8;

    const float* W0  = which ? Wim : Wre;
    const float* W1p = which ? Wre : Wim;
    const float  sgn = which ? 1.0f : -1.0f;

    float acc[8][8];
    #pragma unroll
    for (int i = 0; i < 8; i++)
        #pragma unroll
        for (int j = 0; j < 8; j++) acc[i][j] = 0.0f;

    for (int k0 = 0; k0 < 514; k0 += 8) {
        #pragma unroll
        for (int j = 0; j < 4; j++) {
            int k = k0 + lk4 + j;
            float a = 0.0f, w = 0.0f;
            if (k < 257) {
                a = xre[(size_t)(m0 + lr) * FBINS + k];
                w = W0 [(size_t)(n0 + lr) * FBINS + k];
            } else if (k < 514) {
                a = xim[(size_t)(m0 + lr) * FBINS + (k - 257)];
                w = sgn * W1p[(size_t)(n0 + lr) * FBINS + (k - 257)];
            }
            As[lk4 + j][lr] = a;
            Bs[lk4 + j][lr] = w;
        }
        __syncthreads();
        #pragma unroll
        for (int kk = 0; kk < 8; kk++) {
            float a[8], b[8];
            #pragma unroll
            for (int i = 0; i < 8; i++) a[i] = As[kk][tm + i];
            #pragma unroll
            for (int i = 0; i < 8; i++) b[i] = Bs[kk][tn + i];
            #pragma unroll
            for (int i = 0; i < 8; i++)
                #pragma unroll
                for (int j = 0; j < 8; j++)
                    acc[i][j] = fmaf(a[i], b[j], acc[i][j]);
        }
        __syncthreads();
    }

    const float* bias = which ? bim : bre;
    float* out = g_act + (size_t)which * EMB_M * DM;
    #pragma unroll
    for (int i = 0; i < 8; i++)
        #pragma unroll
        for (int j = 0; j < 8; j++)
            out[(size_t)(m0 + tm + i) * DM + (n0 + tn + j)] =
                acc[i][j] + bias[n0 + tn + j];
}

// ---------------- attention + residual ----------------
// y(s,b,c,d) = act[((s*64+b)*862+c)*256+d]*al[d]+bt[d]
// src[B,c,d] = y(B,c,d) + o_{s}(b, c2, d2),  t=c*256+d, c2=t%862, d2=t/862
// o_re = 0.25*((qr*kr - qi*ki) - (qr*ki - qi*kr))*qr
// o_im = 0.25*((qr*kr - qi*ki) + (qr*ki - qi*kr))*qr
__global__ void k_attn(const float* __restrict__ act, float* __restrict__ src)
{
    size_t e = (size_t)blockIdx.x * blockDim.x + threadIdx.x;
    if (e >= (size_t)MROWS * DM) return;
    int d = (int)(e & 255);
    size_t r = e >> 8;
    int c  = (int)(r % CC);
    int B_ = (int)(r / CC);
    int s = B_ >> 6;
    int b = B_ & 63;

    const float ald = g_al[d], btd = g_bt[d];
    float yv = act[e] * ald + btd;

    int t  = c * DM + d;
    int c2 = t % CC;
    int d2 = t / CC;
    int c3 = (CC - 1) - c2;
    int d3 = (DM - 1) - d2;

    float al2 = g_al[d2], bt2 = g_bt[d2];
    float al3 = g_al[d3], bt3 = g_bt[d3];

    size_t base0 = ((size_t)b * CC) * DM;                 // half 0
    size_t base1 = ((size_t)(64 + b) * CC) * DM;          // half 1

    float qr = act[base0 + (size_t)c2 * DM + d2] * al2 + bt2;
    float qi = act[base1 + (size_t)c2 * DM + d2] * al2 + bt2;
    float kr = act[base0 + (size_t)c3 * DM + d3] * al3 + bt3;
    float ki = act[base1 + (size_t)c3 * DM + d3] * al3 + bt3;

    float asr = qr * kr - qi * ki;
    float asi = qr * ki - qi * kr;
    float o = 0.25f * (s == 0 ? (asr - asi) : (asr + asi)) * qr;

    src[e] = yv + o;
}

// ---------------- batchnorm stats (deterministic two-stage) ----------------
__global__ void k_stats(const float* __restrict__ buf)
{
    int ch = threadIdx.x;
    int blk = blockIdx.x;
    float s = 0.0f, q = 0.0f;
    size_t row0 = (size_t)blk * ROWS_PER_STATB;
    for (int i = 0; i < ROWS_PER_STATB; i++) {
        float v = buf[(row0 + i) * DM + ch];
        s += v;
        q += v * v;
    }
    g_psum[blk * DM + ch] = s;
    g_psq [blk * DM + ch] = q;
}

__global__ void k_finalize(const float* __restrict__ gamma,
                           const float* __restrict__ beta)
{
    int ch = threadIdx.x;
    float s = 0.0f, q = 0.0f;
    for (int i = 0; i < NSTATB; i++) {
        s += g_psum[i * DM + ch];
        q += g_psq [i * DM + ch];
    }
    const float inv = 1.0f / (float)MROWS;
    float m = s * inv;
    float v = q * inv - m * m;
    float al = gamma[ch] * rsqrtf(v + EPSV);
    g_al[ch] = al;
    g_bt[ch] = beta[ch] - m * al;
}

// ---------------- FF GEMM 1: ff = gelu(norm(src) @ W1^T + b1) ----------------
// M=110336, N=512, K=256. Norm affine fused into A-tile load.
__global__ __launch_bounds__(256) void k_ff1(
    const float* __restrict__ src, const float* __restrict__ W,
    const float* __restrict__ bias, float* __restrict__ ff)
{
    __shared__ float As[8][128];
    __shared__ float Bs[8][128];
    const int tid = threadIdx.x;
    const int m0 = blockIdx.y * 128;
    const int n0 = blockIdx.x * 128;
    const int lr  = tid >> 1;
    const int lk4 = (tid & 1) * 4;
    const int tm = (tid >> 4) * 8;
    const int tn = (tid & 15) * 8;

    float acc[8][8];
    #pragma unroll
    for (int i = 0; i < 8; i++)
        #pragma unroll
        for (int j = 0; j < 8; j++) acc[i][j] = 0.0f;

    for (int k0 = 0; k0 < DM; k0 += 8) {
        float4 av = *(const float4*)&src[(size_t)(m0 + lr) * DM + k0 + lk4];
        float4 bv = *(const float4*)&W  [(size_t)(n0 + lr) * DM + k0 + lk4];
        int kb = k0 + lk4;
        As[lk4 + 0][lr] = av.x * g_al[kb + 0] + g_bt[kb + 0];
        As[lk4 + 1][lr] = av.y * g_al[kb + 1] + g_bt[kb + 1];
        As[lk4 + 2][lr] = av.z * g_al[kb + 2] + g_bt[kb + 2];
        As[lk4 + 3][lr] = av.w * g_al[kb + 3] + g_bt[kb + 3];
        Bs[lk4 + 0][lr] = bv.x;
        Bs[lk4 + 1][lr] = bv.y;
        Bs[lk4 + 2][lr] = bv.z;
        Bs[lk4 + 3][lr] = bv.w;
        __syncthreads();
        #pragma unroll
        for (int kk = 0; kk < 8; kk++) {
            float a[8], b[8];
            #pragma unroll
            for (int i = 0; i < 8; i++) a[i] = As[kk][tm + i];
            #pragma unroll
            for (int i = 0; i < 8; i++) b[i] = Bs[kk][tn + i];
            #pragma unroll
            for (int i = 0; i < 8; i++)
                #pragma unroll
                for (int j = 0; j < 8; j++)
                    acc[i][j] = fmaf(a[i], b[j], acc[i][j]);
        }
        __syncthreads();
    }

    #pragma unroll
    for (int i = 0; i < 8; i++)
        #pragma unroll
        for (int j = 0; j < 8; j++) {
            float h = acc[i][j] + bias[n0 + tn + j];
            float g = 0.5f * h * (1.0f + erff(h * 0.70710678118654752f));
            ff[(size_t)(m0 + tm + i) * DFF + (n0 + tn + j)] = g;
        }
}

// ---------------- FF GEMM 2: act = norm(src) + ff @ W2^T + b2 ----------------
// M=110336, N=256, K=512. Residual (normalized src) fused into epilogue.
__global__ __launch_bounds__(256) void k_ff2(
    const float* __restrict__ ff, const float* __restrict__ W,
    const float* __restrict__ bias, const float* __restrict__ src,
    float* __restrict__ out)
{
    __shared__ float As[8][128];
    __shared__ float Bs[8][128];
    const int tid = threadIdx.x;
    const int m0 = blockIdx.y * 128;
    const int n0 = blockIdx.x * 128;
    const int lr  = tid >> 1;
    const int lk4 = (tid & 1) * 4;
    const int tm = (tid >> 4) * 8;
    const int tn = (tid & 15) * 8;

    float acc[8][8];
    #pragma unroll
    for (int i = 0; i < 8; i++)
        #pragma unroll
        for (int j = 0; j < 8; j++) acc[i][j] = 0.0f;

    for (int k0 = 0; k0 < DFF; k0 += 8) {
        float4 av = *(const float4*)&ff[(size_t)(m0 + lr) * DFF + k0 + lk4];
        float4 bv = *(const float4*)&W [(size_t)(n0 + lr) * DFF + k0 + lk4];
        As[lk4 + 0][lr] = av.x;
        As[lk4 + 1][lr] = av.y;
        As[lk4 + 2][lr] = av.z;
        As[lk4 + 3][lr] = av.w;
        Bs[lk4 + 0][lr] = bv.x;
        Bs[lk4 + 1][lr] = bv.y;
        Bs[lk4 + 2][lr] = bv.z;
        Bs[lk4 + 3][lr] = bv.w;
        __syncthreads();
        #pragma unroll
        for (int kk = 0; kk < 8; kk++) {
            float a[8], b[8];
            #pragma unroll
            for (int i = 0; i < 8; i++) a[i] = As[kk][tm + i];
            #pragma unroll
            for (int i = 0; i < 8; i++) b[i] = Bs[kk][tn + i];
            #pragma unroll
            for (int i = 0; i < 8; i++)
                #pragma unroll
                for (int j = 0; j < 8; j++)
                    acc[i][j] = fmaf(a[i], b[j], acc[i][j]);
        }
        __syncthreads();
    }

    #pragma unroll
    for (int i = 0; i < 8; i++)
        #pragma unroll
        for (int j = 0; j < 8; j++) {
            int n = n0 + tn + j;
            size_t m = (size_t)(m0 + tm + i);
            float res = src[m * DM + n] * g_al[n] + g_bt[n];
            out[m * DM + n] = acc[i][j] + bias[n] + res;
        }
}

// ---------------- final output: stack([y[:64], y[64:]], -1) ----------------
__global__ void k_out(const float* __restrict__ act, float* __restrict__ out)
{
    size_t e = (size_t)blockIdx.x * blockDim.x + threadIdx.x;
    if (e >= (size_t)BB * CC * DM) return;
    int d = (int)(e & 255);
    size_t r = e >> 8;                 // b*862 + c
    float al = g_al[d], bt = g_bt[d];
    float v0 = act[r * DM + d] * al + bt;
    float v1 = act[((size_t)EMB_M + r) * DM + d] * al + bt;
    float2 pair = make_float2(v0, v1);
    *(float2*)&out[2 * e] = pair;
}

// ---------------- launch ----------------
extern "C" void kernel_launch(void* const* d_in, const int* in_sizes, int n_in,
                              void* d_out, int out_size)
{
    const float* x_re   = (const float*)d_in[0];
    const float* x_im   = (const float*)d_in[1];
    const float* embWre = (const float*)d_in[2];
    const float* embWim = (const float*)d_in[3];
    const float* embbre = (const float*)d_in[4];
    const float* embbim = (const float*)d_in[5];
    const float* W1     = (const float*)d_in[6];
    const float* b1     = (const float*)d_in[7];
    const float* W2     = (const float*)d_in[8];
    const float* b2     = (const float*)d_in[9];
    const float* gamma1 = (const float*)d_in[10];
    const float* beta1  = (const float*)d_in[11];
    const float* gamma2 = (const float*)d_in[12];
    const float* beta2  = (const float*)d_in[13];
    float* out = (float*)d_out;

    float* act = nullptr; float* src = nullptr; float* ff = nullptr;
    cudaGetSymbolAddress((void**)&act, g_act);
    cudaGetSymbolAddress((void**)&src, g_src);
    cudaGetSymbolAddress((void**)&ff,  g_ff);

    k_init_affine<<<1, DM>>>();

    // embedding
    {
        dim3 grid(DM / 128, EMB_M / 128);
        k_embed_gemm<<<grid, 256>>>(x_re, x_im, embWre, embWim, embbre, embbim, 0);
        k_embed_gemm<<<grid, 256>>>(x_re, x_im, embWre, embWim, embbre, embbim, 1);
    }

    const size_t NE = (size_t)MROWS * DM;
    const int TPB = 256;
    const int attn_blocks = (int)((NE + TPB - 1) / TPB);

    for (int l = 0; l < NL; l++) {
        const float* W1l = W1 + (size_t)l * DFF * DM;
        const float* b1l = b1 + (size_t)l * DFF;
        const float* W2l = W2 + (size_t)l * DM * DFF;
        const float* b2l = b2 + (size_t)l * DM;

        // attention + residual (reads act with current affine, writes src)
        k_attn<<<attn_blocks, TPB>>>(act, src);

        // batchnorm1 -> affine
        k_stats<<<NSTATB, DM>>>(src);
        k_finalize<<<1, DM>>>(gamma1 + l * DM, beta1 + l * DM);

        // ff
        {
            dim3 g1(DFF / 128, MROWS / 128);
            k_ff1<<<g1, 256>>>(src, W1l, b1l, ff);
            dim3 g2(DM / 128, MROWS / 128);
            k_ff2<<<g2, 256>>>(ff, W2l, b2l, src, act);
        }

        // batchnorm2 -> affine (consumed by next attn / final output)
        k_stats<<<NSTATB, DM>>>(act);
        k_finalize<<<1, DM>>>(gamma2 + l * DM, beta2 + l * DM);
    }

    const size_t NO = (size_t)BB * CC * DM;
    k_out<<<(int)((NO + TPB - 1) / TPB), TPB>>>(act, out);
}

// round 3
// speedup vs baseline: 2.2509x; 2.2509x over previous
#include <cuda_runtime.h>
#include <math.h>
#include <stdint.h>

// ---------------------------------------------------------------- shapes
#define BB      64
#define CC      862
#define FBINS   257
#define DM      256
#define DFF     512
#define NL      3
#define EPSV    1e-5f

#define EMB_M   (BB*CC)                 // 55168
#define MROWS   (2*BB*CC)               // 110336
#define NSTATB  256
#define ROWS_PER_STATB (MROWS/NSTATB)   // 431

// ---------------------------------------------------------------- scratch
__device__ float g_act[(size_t)MROWS * DM];
__device__ float g_src[(size_t)MROWS * DM];
__device__ float g_ff [(size_t)MROWS * DFF];
__device__ float g_psum[NSTATB * DM];
__device__ float g_psq [NSTATB * DM];
__device__ float g_al[DM];
__device__ float g_bt[DM];

// ---------------------------------------------------------------- helpers
__device__ __forceinline__ uint32_t f2tf32(float x) {
    uint32_t r;
    asm("cvt.rna.tf32.f32 %0, %1;" : "=r"(r) : "f"(x));
    return r;
}

__device__ __forceinline__ void mma8(float* c,
    uint32_t a0, uint32_t a1, uint32_t a2, uint32_t a3,
    uint32_t b0, uint32_t b1)
{
    asm volatile(
        "mma.sync.aligned.m16n8k8.row.col.f32.tf32.tf32.f32 "
        "{%0,%1,%2,%3}, {%4,%5,%6,%7}, {%8,%9}, {%0,%1,%2,%3};"
        : "+f"(c[0]), "+f"(c[1]), "+f"(c[2]), "+f"(c[3])
        : "r"(a0), "r"(a1), "r"(a2), "r"(a3), "r"(b0), "r"(b1));
}

__device__ __forceinline__ float gelu_exact(float h) {
    return 0.5f * h * (1.0f + erff(h * 0.70710678118654752f));
}

// ---------------------------------------------------------------- misc kernels
__global__ void k_init_affine() { g_al[threadIdx.x] = 1.0f; g_bt[threadIdx.x] = 0.0f; }

// paired attention + residual: one thread does both halves (s=0,1)
__global__ void k_attn2(const float* __restrict__ act, float* __restrict__ src)
{
    size_t e = (size_t)blockIdx.x * blockDim.x + threadIdx.x;
    if (e >= (size_t)EMB_M * DM) return;
    int d = (int)(e & 255);
    size_t r = e >> 8;
    int c = (int)(r % CC);
    int b = (int)(r / CC);

    const float ald = g_al[d], btd = g_bt[d];
    size_t e1 = e + (size_t)EMB_M * DM;
    float y0 = act[e]  * ald + btd;
    float y1 = act[e1] * ald + btd;

    int t  = c * DM + d;
    int c2 = t % CC;
    int d2 = t / CC;
    int c3 = (CC - 1) - c2;
    int d3 = (DM - 1) - d2;

    float al2 = g_al[d2], bt2 = g_bt[d2];
    float al3 = g_al[d3], bt3 = g_bt[d3];

    size_t base0 = ((size_t)b * CC) * DM;
    size_t base1 = ((size_t)(64 + b) * CC) * DM;

    float qr = act[base0 + (size_t)c2 * DM + d2] * al2 + bt2;
    float qi = act[base1 + (size_t)c2 * DM + d2] * al2 + bt2;
    float kr = act[base0 + (size_t)c3 * DM + d3] * al3 + bt3;
    float ki = act[base1 + (size_t)c3 * DM + d3] * al3 + bt3;

    float asr = qr * kr - qi * ki;
    float asi = qr * ki - qi * kr;
    src[e]  = y0 + 0.25f * (asr - asi) * qr;
    src[e1] = y1 + 0.25f * (asr + asi) * qr;
}

__global__ void k_stats(const float* __restrict__ buf)
{
    int ch = threadIdx.x;
    int blk = blockIdx.x;
    float s = 0.0f, q = 0.0f;
    size_t row0 = (size_t)blk * ROWS_PER_STATB;
    for (int i = 0; i < ROWS_PER_STATB; i++) {
        float v = buf[(row0 + i) * DM + ch];
        s += v; q += v * v;
    }
    g_psum[blk * DM + ch] = s;
    g_psq [blk * DM + ch] = q;
}

__global__ void k_finalize(const float* __restrict__ gamma, const float* __restrict__ beta)
{
    int ch = threadIdx.x;
    float s = 0.0f, q = 0.0f;
    for (int i = 0; i < NSTATB; i++) { s += g_psum[i * DM + ch]; q += g_psq[i * DM + ch]; }
    const float inv = 1.0f / (float)MROWS;
    float m = s * inv;
    float v = q * inv - m * m;
    float al = gamma[ch] * rsqrtf(v + EPSV);
    g_al[ch] = al;
    g_bt[ch] = beta[ch] - m * al;
}

__global__ void k_out(const float* __restrict__ act, float* __restrict__ out)
{
    size_t e = (size_t)blockIdx.x * blockDim.x + threadIdx.x;
    if (e >= (size_t)BB * CC * DM) return;
    int d = (int)(e & 255);
    size_t r = e >> 8;
    float al = g_al[d], bt = g_bt[d];
    float v0 = act[r * DM + d] * al + bt;
    float v1 = act[((size_t)EMB_M + r) * DM + d] * al + bt;
    *(float2*)&out[2 * e] = make_float2(v0, v1);
}

// ---------------------------------------------------------------- tf32 mma GEMM
// MODE 0: ff1  : out[M,512] = gelu( (src*al+bt)[M,256] @ W1^T + b1 )
// MODE 1: ff2  : out[M,256] = ff[M,512] @ W2^T + b2 + (src*al+bt)
// MODE 2: embed: out[55168,256] (+which offset) = [xre|xim] @ [W0|sgn*W1]^T + bias
//
// Block tile 128x128, BK=16, 256 threads = 8 warps (2 along M x 4 along N),
// warp tile 64x32 -> 4x4 m16n8k8 fragments. Double-buffered smem, (k,k+4)
// pairs stored adjacent so fragment loads are LDS.64.
template<int MODE>
__global__ __launch_bounds__(256) void k_gemm(
    const float* __restrict__ A,  const float* __restrict__ Bm,
    const float* __restrict__ bias, const float* __restrict__ src,
    float* __restrict__ out,
    const float* __restrict__ xre, const float* __restrict__ xim,
    const float* __restrict__ Wre, const float* __restrict__ Wim,
    const float* __restrict__ bre, const float* __restrict__ bim)
{
    constexpr int KK   = (MODE == 0) ? DM : (MODE == 1) ? DFF : 528;
    constexpr int NKB  = KK / 16;
    constexpr int ASTR = (MODE == 0) ? DM : DFF;   // unused for MODE 2
    constexpr int OSTR = (MODE == 0) ? DFF : DM;

    __shared__ uint32_t sA[2][2][128][8];
    __shared__ uint32_t sB[2][2][128][8];

    const int tid  = threadIdx.x;
    const int lane = tid & 31;
    const int w    = tid >> 5;
    const int wm   = w & 1;      // 0..1
    const int wn   = w >> 1;     // 0..3
    const int m0   = blockIdx.y * 128;
    const int n0   = blockIdx.x * 128;
    const int g    = lane >> 2;  // group id 0..7
    const int tg   = lane & 3;   // thread-in-group 0..3

    // MODE 2 specifics
    const int which = (MODE == 2) ? blockIdx.z : 0;
    const float* W0  = (MODE == 2) ? (which ? Wim : Wre) : nullptr;
    const float* W1p = (MODE == 2) ? (which ? Wre : Wim) : nullptr;
    const float  sgn = which ? 1.0f : -1.0f;

    float acc[4][4][4];
    #pragma unroll
    for (int mt = 0; mt < 4; mt++)
        #pragma unroll
        for (int nt = 0; nt < 4; nt++)
            #pragma unroll
            for (int i = 0; i < 4; i++) acc[mt][nt][i] = 0.0f;

    // staging registers
    float4 ra[2], rb[2];        // MODE 0/1
    float  ea[8], eb[8];        // MODE 2

    // ---- load (global -> regs) for chunk kb
    auto ldg = [&](int kb) {
        if (MODE == 2) {
            #pragma unroll
            for (int it = 0; it < 8; it++) {
                int idx = it * 256 + tid;
                int row = idx >> 4, kl = idx & 15;
                int kg = kb * 16 + kl;
                float a = 0.0f, b = 0.0f;
                if (kg < FBINS) {
                    a = xre[(size_t)(m0 + row) * FBINS + kg];
                    b = W0 [(size_t)(n0 + row) * FBINS + kg];
                } else if (kg < 2 * FBINS) {
                    a = xim[(size_t)(m0 + row) * FBINS + (kg - FBINS)];
                    b = sgn * W1p[(size_t)(n0 + row) * FBINS + (kg - FBINS)];
                }
                ea[it] = a; eb[it] = b;
            }
        } else {
            #pragma unroll
            for (int it = 0; it < 2; it++) {
                int idx = it * 256 + tid;
                int row = idx >> 2, kq = idx & 3;
                int kg = kb * 16 + kq * 4;
                ra[it] = *(const float4*)&A [(size_t)(m0 + row) * ASTR + kg];
                rb[it] = *(const float4*)&Bm[(size_t)(n0 + row) * ASTR + kg];
                if (MODE == 0) {
                    float4 al = *(const float4*)&g_al[kg];
                    float4 bt = *(const float4*)&g_bt[kg];
                    ra[it].x = ra[it].x * al.x + bt.x;
                    ra[it].y = ra[it].y * al.y + bt.y;
                    ra[it].z = ra[it].z * al.z + bt.z;
                    ra[it].w = ra[it].w * al.w + bt.w;
                }
            }
        }
    };

    // ---- store (regs -> smem buf), tf32-converted, (k,k+4)-paired layout
    auto sts = [&](int buf) {
        if (MODE == 2) {
            #pragma unroll
            for (int it = 0; it < 8; it++) {
                int idx = it * 256 + tid;
                int row = idx >> 4, kl = idx & 15;
                int panel = kl >> 3, kk = kl & 7;
                int col = (kk & 3) * 2 + (kk >> 2);
                sA[buf][panel][row][col] = f2tf32(ea[it]);
                sB[buf][panel][row][col] = f2tf32(eb[it]);
            }
        } else {
            #pragma unroll
            for (int it = 0; it < 2; it++) {
                int idx = it * 256 + tid;
                int row = idx >> 2, kq = idx & 3;
                int panel = kq >> 1, par = kq & 1;
                sA[buf][panel][row][0 + par] = f2tf32(ra[it].x);
                sA[buf][panel][row][2 + par] = f2tf32(ra[it].y);
                sA[buf][panel][row][4 + par] = f2tf32(ra[it].z);
                sA[buf][panel][row][6 + par] = f2tf32(ra[it].w);
                sB[buf][panel][row][0 + par] = f2tf32(rb[it].x);
                sB[buf][panel][row][2 + par] = f2tf32(rb[it].y);
                sB[buf][panel][row][4 + par] = f2tf32(rb[it].z);
                sB[buf][panel][row][6 + par] = f2tf32(rb[it].w);
            }
        }
    };

    // ---- compute chunk from smem buf
    auto compute = [&](int buf) {
        #pragma unroll
        for (int p = 0; p < 2; p++) {
            uint32_t af[4][4];
            #pragma unroll
            for (int mt = 0; mt < 4; mt++) {
                int r = wm * 64 + mt * 16 + g;
                uint2 lo = *(const uint2*)&sA[buf][p][r][tg * 2];
                uint2 hi = *(const uint2*)&sA[buf][p][r + 8][tg * 2];
                af[mt][0] = lo.x; af[mt][2] = lo.y;
                af[mt][1] = hi.x; af[mt][3] = hi.y;
            }
            #pragma unroll
            for (int nt = 0; nt < 4; nt++) {
                int n = wn * 32 + nt * 8 + g;
                uint2 bb = *(const uint2*)&sB[buf][p][n][tg * 2];
                #pragma unroll
                for (int mt = 0; mt < 4; mt++)
                    mma8(acc[mt][nt], af[mt][0], af[mt][1], af[mt][2], af[mt][3],
                         bb.x, bb.y);
            }
        }
    };

    // ---- pipelined main loop
    ldg(0); sts(0);
    __syncthreads();
    #pragma unroll 1
    for (int kb = 0; kb < NKB; kb++) {
        int cur = kb & 1;
        if (kb + 1 < NKB) ldg(kb + 1);
        compute(cur);
        if (kb + 1 < NKB) sts(cur ^ 1);
        __syncthreads();
    }

    // ---- epilogue
    const float* biasp = (MODE == 2) ? (which ? bim : bre) : bias;
    float* outp = (MODE == 2) ? (out + (size_t)which * EMB_M * DM) : out;

    #pragma unroll
    for (int mt = 0; mt < 4; mt++) {
        int r0 = m0 + wm * 64 + mt * 16 + g;
        int r1 = r0 + 8;
        #pragma unroll
        for (int nt = 0; nt < 4; nt++) {
            int cb = n0 + wn * 32 + nt * 8 + tg * 2;
            float* c = acc[mt][nt];
            float2 bi = *(const float2*)&biasp[cb];
            if (MODE == 0) {
                float2 o0 = make_float2(gelu_exact(c[0] + bi.x), gelu_exact(c[1] + bi.y));
                float2 o1 = make_float2(gelu_exact(c[2] + bi.x), gelu_exact(c[3] + bi.y));
                *(float2*)&outp[(size_t)r0 * OSTR + cb] = o0;
                *(float2*)&outp[(size_t)r1 * OSTR + cb] = o1;
            } else if (MODE == 1) {
                float2 al = *(const float2*)&g_al[cb];
                float2 bt = *(const float2*)&g_bt[cb];
                float2 s0 = *(const float2*)&src[(size_t)r0 * DM + cb];
                float2 s1 = *(const float2*)&src[(size_t)r1 * DM + cb];
                float2 o0 = make_float2(c[0] + bi.x + s0.x * al.x + bt.x,
                                        c[1] + bi.y + s0.y * al.y + bt.y);
                float2 o1 = make_float2(c[2] + bi.x + s1.x * al.x + bt.x,
                                        c[3] + bi.y + s1.y * al.y + bt.y);
                *(float2*)&outp[(size_t)r0 * OSTR + cb] = o0;
                *(float2*)&outp[(size_t)r1 * OSTR + cb] = o1;
            } else {
                float2 o0 = make_float2(c[0] + bi.x, c[1] + bi.y);
                float2 o1 = make_float2(c[2] + bi.x, c[3] + bi.y);
                *(float2*)&outp[(size_t)r0 * OSTR + cb] = o0;
                *(float2*)&outp[(size_t)r1 * OSTR + cb] = o1;
            }
        }
    }
}

// ---------------------------------------------------------------- launch
extern "C" void kernel_launch(void* const* d_in, const int* in_sizes, int n_in,
                              void* d_out, int out_size)
{
    const float* x_re   = (const float*)d_in[0];
    const float* x_im   = (const float*)d_in[1];
    const float* embWre = (const float*)d_in[2];
    const float* embWim = (const float*)d_in[3];
    const float* embbre = (const float*)d_in[4];
    const float* embbim = (const float*)d_in[5];
    const float* W1     = (const float*)d_in[6];
    const float* b1     = (const float*)d_in[7];
    const float* W2     = (const float*)d_in[8];
    const float* b2     = (const float*)d_in[9];
    const float* gamma1 = (const float*)d_in[10];
    const float* beta1  = (const float*)d_in[11];
    const float* gamma2 = (const float*)d_in[12];
    const float* beta2  = (const float*)d_in[13];
    float* out = (float*)d_out;

    float* act = nullptr; float* src = nullptr; float* ff = nullptr;
    cudaGetSymbolAddress((void**)&act, g_act);
    cudaGetSymbolAddress((void**)&src, g_src);
    cudaGetSymbolAddress((void**)&ff,  g_ff);

    k_init_affine<<<1, DM>>>();

    // embedding: grid (n-tiles=2, m-tiles=431, which=2)
    {
        dim3 grid(2, EMB_M / 128, 2);
        k_gemm<2><<<grid, 256>>>(nullptr, nullptr, nullptr, nullptr, act,
                                 x_re, x_im, embWre, embWim, embbre, embbim);
    }

    const int TPB = 256;
    const int attn_blocks = (int)(((size_t)EMB_M * DM + TPB - 1) / TPB);

    for (int l = 0; l < NL; l++) {
        const float* W1l = W1 + (size_t)l * DFF * DM;
        const float* b1l = b1 + (size_t)l * DFF;
        const float* W2l = W2 + (size_t)l * DM * DFF;
        const float* b2l = b2 + (size_t)l * DM;

        k_attn2<<<attn_blocks, TPB>>>(act, src);

        k_stats<<<NSTATB, DM>>>(src);
        k_finalize<<<1, DM>>>(gamma1 + l * DM, beta1 + l * DM);

        {
            dim3 g1(DFF / 128, MROWS / 128);
            k_gemm<0><<<g1, 256>>>(src, W1l, b1l, nullptr, ff,
                                   nullptr, nullptr, nullptr, nullptr, nullptr, nullptr);
            dim3 g2(DM / 128, MROWS / 128);
            k_gemm<1><<<g2, 256>>>(ff, W2l, b2l, src, act,
                                   nullptr, nullptr, nullptr, nullptr, nullptr, nullptr);
        }

        k_stats<<<NSTATB, DM>>>(act);
        k_finalize<<<1, DM>>>(gamma2 + l * DM, beta2 + l * DM);
    }

    const size_t NO = (size_t)BB * CC * DM;
    k_out<<<(int)((NO + TPB - 1) / TPB), TPB>>>(act, out);
}

// round 4
// speedup vs baseline: 2.2939x; 1.0191x over previous
#include <cuda_runtime.h>
#include <math.h>
#include <stdint.h>

// ---------------------------------------------------------------- shapes
#define BB      64
#define CC      862
#define FBINS   257
#define DM      256
#define DFF     512
#define NL      3
#define EPSV    1e-5f

#define EMB_M   (BB*CC)                 // 55168
#define MROWS   (2*BB*CC)               // 110336
#define NSTATB  431
#define ROWS_PER_STATB 256              // 431*256 = 110336

// ---------------------------------------------------------------- scratch
__device__ float g_act[(size_t)MROWS * DM];
__device__ float g_src[(size_t)MROWS * DM];
__device__ float g_ff [(size_t)MROWS * DFF];   // also reused as P_re/P_im during attn
__device__ float g_psum[NSTATB * DM];
__device__ float g_psq [NSTATB * DM];
__device__ float g_al[DM];
__device__ float g_bt[DM];

// ---------------------------------------------------------------- helpers
__device__ __forceinline__ uint32_t f2tf32(float x) {
    uint32_t r;
    asm("cvt.rna.tf32.f32 %0, %1;" : "=r"(r) : "f"(x));
    return r;
}

__device__ __forceinline__ void mma8(float* c,
    uint32_t a0, uint32_t a1, uint32_t a2, uint32_t a3,
    uint32_t b0, uint32_t b1)
{
    asm volatile(
        "mma.sync.aligned.m16n8k8.row.col.f32.tf32.tf32.f32 "
        "{%0,%1,%2,%3}, {%4,%5,%6,%7}, {%8,%9}, {%0,%1,%2,%3};"
        : "+f"(c[0]), "+f"(c[1]), "+f"(c[2]), "+f"(c[3])
        : "r"(a0), "r"(a1), "r"(a2), "r"(a3), "r"(b0), "r"(b1));
}

__device__ __forceinline__ float gelu_exact(float h) {
    return 0.5f * h * (1.0f + erff(h * 0.70710678118654752f));
}

// ---------------------------------------------------------------- misc kernels
__global__ void k_init_affine() { g_al[threadIdx.x] = 1.0f; g_bt[threadIdx.x] = 0.0f; }

// ---------------- attention pass 1: compute o_re/o_im, store TRANSPOSED ----
// P_re[b][d2][c2], P_im[b][d2][c2]; reads are coalesced along d2, writes along c2.
__global__ __launch_bounds__(256) void k_attn_pre(
    const float* __restrict__ act, float* __restrict__ Pre, float* __restrict__ Pim)
{
    __shared__ float sre[32][33];
    __shared__ float sim[32][33];
    const int c0 = blockIdx.x * 32;
    const int d0 = blockIdx.y * 32;
    const int b  = blockIdx.z;
    const int tx = threadIdx.x & 31;
    const int ty = threadIdx.x >> 5;

    const int d2 = d0 + tx;
    const int d3 = (DM - 1) - d2;
    const float al2 = g_al[d2], bt2 = g_bt[d2];
    const float al3 = g_al[d3], bt3 = g_bt[d3];

    #pragma unroll
    for (int rr = 0; rr < 4; rr++) {
        int c2l = ty + rr * 8;
        int c2 = c0 + c2l;
        if (c2 < CC) {
            int c3 = (CC - 1) - c2;
            float qr = act[((size_t)b        * CC + c2) * DM + d2] * al2 + bt2;
            float qi = act[((size_t)(64 + b) * CC + c2) * DM + d2] * al2 + bt2;
            float kr = act[((size_t)b        * CC + c3) * DM + d3] * al3 + bt3;
            float ki = act[((size_t)(64 + b) * CC + c3) * DM + d3] * al3 + bt3;
            float asr = qr * kr - qi * ki;
            float asi = qr * ki - qi * kr;
            sre[c2l][tx] = 0.25f * (asr - asi) * qr;
            sim[c2l][tx] = 0.25f * (asr + asi) * qr;
        }
    }
    __syncthreads();
    #pragma unroll
    for (int rr = 0; rr < 4; rr++) {
        int d2l = ty + rr * 8;
        int c2 = c0 + tx;
        if (c2 < CC) {
            size_t o = ((size_t)b * DM + (d0 + d2l)) * CC + c2;
            Pre[o] = sre[tx][d2l];
            Pim[o] = sim[tx][d2l];
        }
    }
}

// ---------------- attention pass 2: src = y*affine + P (fully linear) ------
__global__ void k_attn_post(
    const float* __restrict__ act, const float* __restrict__ Pre,
    const float* __restrict__ Pim, float* __restrict__ src)
{
    size_t idx = (size_t)blockIdx.x * blockDim.x + threadIdx.x;   // float4 index
    if (idx >= (size_t)EMB_M * DM / 4) return;
    size_t e = idx * 4;
    int d = (int)(e & 255);
    float4 al = *(const float4*)&g_al[d];
    float4 bt = *(const float4*)&g_bt[d];

    const float4* a4 = (const float4*)act;
    float4 a0 = a4[idx];
    float4 a1 = a4[idx + (size_t)EMB_M * DM / 4];
    float4 p0 = ((const float4*)Pre)[idx];
    float4 p1 = ((const float4*)Pim)[idx];

    float4 o0, o1;
    o0.x = a0.x * al.x + bt.x + p0.x;  o0.y = a0.y * al.y + bt.y + p0.y;
    o0.z = a0.z * al.z + bt.z + p0.z;  o0.w = a0.w * al.w + bt.w + p0.w;
    o1.x = a1.x * al.x + bt.x + p1.x;  o1.y = a1.y * al.y + bt.y + p1.y;
    o1.z = a1.z * al.z + bt.z + p1.z;  o1.w = a1.w * al.w + bt.w + p1.w;

    ((float4*)src)[idx] = o0;
    ((float4*)src)[idx + (size_t)EMB_M * DM / 4] = o1;
}

__global__ void k_stats(const float* __restrict__ buf)
{
    int ch = threadIdx.x;
    int blk = blockIdx.x;
    float s = 0.0f, q = 0.0f;
    size_t row0 = (size_t)blk * ROWS_PER_STATB;
    #pragma unroll 8
    for (int i = 0; i < ROWS_PER_STATB; i++) {
        float v = buf[(row0 + i) * DM + ch];
        s += v; q += v * v;
    }
    g_psum[blk * DM + ch] = s;
    g_psq [blk * DM + ch] = q;
}

__global__ void k_finalize(const float* __restrict__ gamma, const float* __restrict__ beta)
{
    int ch = threadIdx.x;
    float s = 0.0f, q = 0.0f;
    for (int i = 0; i < NSTATB; i++) { s += g_psum[i * DM + ch]; q += g_psq[i * DM + ch]; }
    const float inv = 1.0f / (float)MROWS;
    float m = s * inv;
    float v = q * inv - m * m;
    float al = gamma[ch] * rsqrtf(v + EPSV);
    g_al[ch] = al;
    g_bt[ch] = beta[ch] - m * al;
}

__global__ void k_out(const float* __restrict__ act, float* __restrict__ out)
{
    size_t e = (size_t)blockIdx.x * blockDim.x + threadIdx.x;
    if (e >= (size_t)BB * CC * DM) return;
    int d = (int)(e & 255);
    size_t r = e >> 8;
    float al = g_al[d], bt = g_bt[d];
    float v0 = act[r * DM + d] * al + bt;
    float v1 = act[((size_t)EMB_M + r) * DM + d] * al + bt;
    *(float2*)&out[2 * e] = make_float2(v0, v1);
}

// ---------------------------------------------------------------- ff GEMMs (tf32 mma)
// MODE 0: ff1 : out[M,512] = gelu( (src*al+bt)[M,256] @ W1^T + b1 )
// MODE 1: ff2 : out[M,256] = ff[M,512] @ W2^T + b2 + (src*al+bt)
// 128x128 CTA tile, BK=16, 4-buffer ring, one __syncthreads per 2 chunks.
template<int MODE>
__global__ __launch_bounds__(256) void k_ffgemm(
    const float* __restrict__ A,  const float* __restrict__ Bm,
    const float* __restrict__ bias, const float* __restrict__ src,
    float* __restrict__ out)
{
    constexpr int KK   = (MODE == 0) ? DM : DFF;
    constexpr int NKB  = KK / 16;          // 16 or 32 (even)
    constexpr int ASTR = KK;
    constexpr int OSTR = (MODE == 0) ? DFF : DM;

    extern __shared__ uint32_t dynsm[];
    typedef uint32_t SBuf[2][128][8];
    SBuf* sA = (SBuf*)dynsm;                       // [4] buffers
    SBuf* sB = (SBuf*)(dynsm + 4 * 2 * 128 * 8);   // [4] buffers

    const int tid  = threadIdx.x;
    const int lane = tid & 31;
    const int w    = tid >> 5;
    const int wm   = w & 1;
    const int wn   = w >> 1;
    const int m0   = blockIdx.y * 128;
    const int n0   = blockIdx.x * 128;
    const int g    = lane >> 2;
    const int tg   = lane & 3;

    float acc[4][4][4];
    #pragma unroll
    for (int mt = 0; mt < 4; mt++)
        #pragma unroll
        for (int nt = 0; nt < 4; nt++)
            #pragma unroll
            for (int i = 0; i < 4; i++) acc[mt][nt][i] = 0.0f;

    float4 ra[2][2], rb[2][2];   // [slot][it]

    auto ldg = [&](int kb, int s) {
        #pragma unroll
        for (int it = 0; it < 2; it++) {
            int idx = it * 256 + tid;
            int row = idx >> 2, kq = idx & 3;
            int kg = kb * 16 + kq * 4;
            ra[s][it] = *(const float4*)&A [(size_t)(m0 + row) * ASTR + kg];
            rb[s][it] = *(const float4*)&Bm[(size_t)(n0 + row) * ASTR + kg];
            if (MODE == 0) {
                float4 al = *(const float4*)&g_al[kg];
                float4 bt = *(const float4*)&g_bt[kg];
                ra[s][it].x = ra[s][it].x * al.x + bt.x;
                ra[s][it].y = ra[s][it].y * al.y + bt.y;
                ra[s][it].z = ra[s][it].z * al.z + bt.z;
                ra[s][it].w = ra[s][it].w * al.w + bt.w;
            }
        }
    };

    auto sts = [&](int buf, int s) {
        #pragma unroll
        for (int it = 0; it < 2; it++) {
            int idx = it * 256 + tid;
            int row = idx >> 2, kq = idx & 3;
            int panel = kq >> 1, par = kq & 1;
            sA[buf][panel][row][0 + par] = f2tf32(ra[s][it].x);
            sA[buf][panel][row][2 + par] = f2tf32(ra[s][it].y);
            sA[buf][panel][row][4 + par] = f2tf32(ra[s][it].z);
            sA[buf][panel][row][6 + par] = f2tf32(ra[s][it].w);
            sB[buf][panel][row][0 + par] = f2tf32(rb[s][it].x);
            sB[buf][panel][row][2 + par] = f2tf32(rb[s][it].y);
            sB[buf][panel][row][4 + par] = f2tf32(rb[s][it].z);
            sB[buf][panel][row][6 + par] = f2tf32(rb[s][it].w);
        }
    };

    auto compute = [&](int buf) {
        #pragma unroll
        for (int p = 0; p < 2; p++) {
            uint32_t af[4][4];
            #pragma unroll
            for (int mt = 0; mt < 4; mt++) {
                int r = wm * 64 + mt * 16 + g;
                uint2 lo = *(const uint2*)&sA[buf][p][r][tg * 2];
                uint2 hi = *(const uint2*)&sA[buf][p][r + 8][tg * 2];
                af[mt][0] = lo.x; af[mt][2] = lo.y;
                af[mt][1] = hi.x; af[mt][3] = hi.y;
            }
            #pragma unroll
            for (int nt = 0; nt < 4; nt++) {
                int n = wn * 32 + nt * 8 + g;
                uint2 bb = *(const uint2*)&sB[buf][p][n][tg * 2];
                #pragma unroll
                for (int mt = 0; mt < 4; mt++)
                    mma8(acc[mt][nt], af[mt][0], af[mt][1], af[mt][2], af[mt][3],
                         bb.x, bb.y);
            }
        }
    };

    ldg(0, 0); ldg(1, 1);
    sts(0, 0); sts(1, 1);
    __syncthreads();
    #pragma unroll 1
    for (int kb = 0; kb < NKB; kb += 2) {
        bool more = (kb + 2 < NKB);
        if (more) { ldg(kb + 2, 0); ldg(kb + 3, 1); }
        compute(kb & 3);
        compute((kb + 1) & 3);
        if (more) { sts((kb + 2) & 3, 0); sts((kb + 3) & 3, 1); }
        __syncthreads();
    }

    // ---- epilogue
    #pragma unroll
    for (int mt = 0; mt < 4; mt++) {
        int r0 = m0 + wm * 64 + mt * 16 + g;
        int r1 = r0 + 8;
        #pragma unroll
        for (int nt = 0; nt < 4; nt++) {
            int cb = n0 + wn * 32 + nt * 8 + tg * 2;
            float* c = acc[mt][nt];
            float2 bi = *(const float2*)&bias[cb];
            if (MODE == 0) {
                float2 o0 = make_float2(gelu_exact(c[0] + bi.x), gelu_exact(c[1] + bi.y));
                float2 o1 = make_float2(gelu_exact(c[2] + bi.x), gelu_exact(c[3] + bi.y));
                *(float2*)&out[(size_t)r0 * OSTR + cb] = o0;
                *(float2*)&out[(size_t)r1 * OSTR + cb] = o1;
            } else {
                float2 al = *(const float2*)&g_al[cb];
                float2 bt = *(const float2*)&g_bt[cb];
                float2 s0 = *(const float2*)&src[(size_t)r0 * DM + cb];
                float2 s1 = *(const float2*)&src[(size_t)r1 * DM + cb];
                float2 o0 = make_float2(c[0] + bi.x + s0.x * al.x + bt.x,
                                        c[1] + bi.y + s0.y * al.y + bt.y);
                float2 o1 = make_float2(c[2] + bi.x + s1.x * al.x + bt.x,
                                        c[3] + bi.y + s1.y * al.y + bt.y);
                *(float2*)&out[(size_t)r0 * OSTR + cb] = o0;
                *(float2*)&out[(size_t)r1 * OSTR + cb] = o1;
            }
        }
    }
}

// ---------------------------------------------------------------- embedding GEMM (proven R3 path)
__global__ __launch_bounds__(256) void k_embed(
    float* __restrict__ out,
    const float* __restrict__ xre, const float* __restrict__ xim,
    const float* __restrict__ Wre, const float* __restrict__ Wim,
    const float* __restrict__ bre, const float* __restrict__ bim)
{
    constexpr int NKB = 33;   // 528 / 16

    __shared__ uint32_t sA[2][2][128][8];
    __shared__ uint32_t sB[2][2][128][8];

    const int tid  = threadIdx.x;
    const int lane = tid & 31;
    const int w    = tid >> 5;
    const int wm   = w & 1;
    const int wn   = w >> 1;
    const int m0   = blockIdx.y * 128;
    const int n0   = blockIdx.x * 128;
    const int g    = lane >> 2;
    const int tg   = lane & 3;

    const int which = blockIdx.z;
    const float* W0  = which ? Wim : Wre;
    const float* W1p = which ? Wre : Wim;
    const float  sgn = which ? 1.0f : -1.0f;

    float acc[4][4][4];
    #pragma unroll
    for (int mt = 0; mt < 4; mt++)
        #pragma unroll
        for (int nt = 0; nt < 4; nt++)
            #pragma unroll
            for (int i = 0; i < 4; i++) acc[mt][nt][i] = 0.0f;

    float ea[8], eb[8];

    auto ldg = [&](int kb) {
        #pragma unroll
        for (int it = 0; it < 8; it++) {
            int idx = it * 256 + tid;
            int row = idx >> 4, kl = idx & 15;
            int kg = kb * 16 + kl;
            float a = 0.0f, b = 0.0f;
            if (kg < FBINS) {
                a = xre[(size_t)(m0 + row) * FBINS + kg];
                b = W0 [(size_t)(n0 + row) * FBINS + kg];
            } else if (kg < 2 * FBINS) {
                a = xim[(size_t)(m0 + row) * FBINS + (kg - FBINS)];
                b = sgn * W1p[(size_t)(n0 + row) * FBINS + (kg - FBINS)];
            }
            ea[it] = a; eb[it] = b;
        }
    };

    auto sts = [&](int buf) {
        #pragma unroll
        for (int it = 0; it < 8; it++) {
            int idx = it * 256 + tid;
            int row = idx >> 4, kl = idx & 15;
            int panel = kl >> 3, kk = kl & 7;
            int col = (kk & 3) * 2 + (kk >> 2);
            sA[buf][panel][row][col] = f2tf32(ea[it]);
            sB[buf][panel][row][col] = f2tf32(eb[it]);
        }
    };

    auto compute = [&](int buf) {
        #pragma unroll
        for (int p = 0; p < 2; p++) {
            uint32_t af[4][4];
            #pragma unroll
            for (int mt = 0; mt < 4; mt++) {
                int r = wm * 64 + mt * 16 + g;
                uint2 lo = *(const uint2*)&sA[buf][p][r][tg * 2];
                uint2 hi = *(const uint2*)&sA[buf][p][r + 8][tg * 2];
                af[mt][0] = lo.x; af[mt][2] = lo.y;
                af[mt][1] = hi.x; af[mt][3] = hi.y;
            }
            #pragma unroll
            for (int nt = 0; nt < 4; nt++) {
                int n = wn * 32 + nt * 8 + g;
                uint2 bb = *(const uint2*)&sB[buf][p][n][tg * 2];
                #pragma unroll
                for (int mt = 0; mt < 4; mt++)
                    mma8(acc[mt][nt], af[mt][0], af[mt][1], af[mt][2], af[mt][3],
                         bb.x, bb.y);
            }
        }
    };

    ldg(0); sts(0);
    __syncthreads();
    #pragma unroll 1
    for (int kb = 0; kb < NKB; kb++) {
        int cur = kb & 1;
        if (kb + 1 < NKB) ldg(kb + 1);
        compute(cur);
        if (kb + 1 < NKB) sts(cur ^ 1);
        __syncthreads();
    }

    const float* biasp = which ? bim : bre;
    float* outp = out + (size_t)which * EMB_M * DM;

    #pragma unroll
    for (int mt = 0; mt < 4; mt++) {
        int r0 = m0 + wm * 64 + mt * 16 + g;
        int r1 = r0 + 8;
        #pragma unroll
        for (int nt = 0; nt < 4; nt++) {
            int cb = n0 + wn * 32 + nt * 8 + tg * 2;
            float* c = acc[mt][nt];
            float2 bi = *(const float2*)&biasp[cb];
            float2 o0 = make_float2(c[0] + bi.x, c[1] + bi.y);
            float2 o1 = make_float2(c[2] + bi.x, c[3] + bi.y);
            *(float2*)&outp[(size_t)r0 * DM + cb] = o0;
            *(float2*)&outp[(size_t)r1 * DM + cb] = o1;
        }
    }
}

// ---------------------------------------------------------------- launch
extern "C" void kernel_launch(void* const* d_in, const int* in_sizes, int n_in,
                              void* d_out, int out_size)
{
    const float* x_re   = (const float*)d_in[0];
    const float* x_im   = (const float*)d_in[1];
    const float* embWre = (const float*)d_in[2];
    const float* embWim = (const float*)d_in[3];
    const float* embbre = (const float*)d_in[4];
    const float* embbim = (const float*)d_in[5];
    const float* W1     = (const float*)d_in[6];
    const float* b1     = (const float*)d_in[7];
    const float* W2     = (const float*)d_in[8];
    const float* b2     = (const float*)d_in[9];
    const float* gamma1 = (const float*)d_in[10];
    const float* beta1  = (const float*)d_in[11];
    const float* gamma2 = (const float*)d_in[12];
    const float* beta2  = (const float*)d_in[13];
    float* out = (float*)d_out;

    float* act = nullptr; float* src = nullptr; float* ff = nullptr;
    cudaGetSymbolAddress((void**)&act, g_act);
    cudaGetSymbolAddress((void**)&src, g_src);
    cudaGetSymbolAddress((void**)&ff,  g_ff);

    const int DYNSM = 4 * 2 * 128 * 8 * 4 * 2;   // 65536 bytes
    cudaFuncSetAttribute(k_ffgemm<0>, cudaFuncAttributeMaxDynamicSharedMemorySize, DYNSM);
    cudaFuncSetAttribute(k_ffgemm<1>, cudaFuncAttributeMaxDynamicSharedMemorySize, DYNSM);

    k_init_affine<<<1, DM>>>();

    {
        dim3 grid(2, EMB_M / 128, 2);
        k_embed<<<grid, 256>>>(act, x_re, x_im, embWre, embWim, embbre, embbim);
    }

    float* Pre = ff;
    float* Pim = ff + (size_t)EMB_M * DM;

    const int post_blocks = (int)(((size_t)EMB_M * DM / 4 + 255) / 256);

    for (int l = 0; l < NL; l++) {
        const float* W1l = W1 + (size_t)l * DFF * DM;
        const float* b1l = b1 + (size_t)l * DFF;
        const float* W2l = W2 + (size_t)l * DM * DFF;
        const float* b2l = b2 + (size_t)l * DM;

        {
            dim3 gpre((CC + 31) / 32, DM / 32, BB);
            k_attn_pre<<<gpre, 256>>>(act, Pre, Pim);
            k_attn_post<<<post_blocks, 256>>>(act, Pre, Pim, src);
        }

        k_stats<<<NSTATB, DM>>>(src);
        k_finalize<<<1, DM>>>(gamma1 + l * DM, beta1 + l * DM);

        {
            dim3 g1(DFF / 128, MROWS / 128);
            k_ffgemm<0><<<g1, 256, DYNSM>>>(src, W1l, b1l, nullptr, ff);
            dim3 g2(DM / 128, MROWS / 128);
            k_ffgemm<1><<<g2, 256, DYNSM>>>(ff, W2l, b2l, src, act);
        }

        k_stats<<<NSTATB, DM>>>(act);
        k_finalize<<<1, DM>>>(gamma2 + l * DM, beta2 + l * DM);
    }

    const size_t NO = (size_t)BB * CC * DM;
    k_out<<<(int)((NO + 255) / 256), 256>>>(act, out);
}

// round 5
// speedup vs baseline: 2.6358x; 1.1490x over previous
#include <cuda_runtime.h>
#include <math.h>
#include <stdint.h>

// ---------------------------------------------------------------- shapes
#define BB      64
#define CC      862
#define FBINS   257
#define DM      256
#define DFF     512
#define NL      3
#define EPSV    1e-5f

#define EMB_M   (BB*CC)                 // 55168
#define MROWS   (2*BB*CC)               // 110336
#define NSTATB  431
#define ROWS_PER_STATB 256              // 431*256 = 110336

// ---------------------------------------------------------------- scratch
__device__ float g_act[(size_t)MROWS * DM];
__device__ float g_src[(size_t)MROWS * DM];
__device__ float g_ff [(size_t)MROWS * DFF];   // also reused as P_re/P_im during attn
__device__ float g_psum[NSTATB * DM];
__device__ float g_psq [NSTATB * DM];
__device__ float g_al[DM];
__device__ float g_bt[DM];

// ---------------------------------------------------------------- helpers
__device__ __forceinline__ uint32_t f2tf32(float x) {
    uint32_t r;
    asm("cvt.rna.tf32.f32 %0, %1;" : "=r"(r) : "f"(x));
    return r;
}

__device__ __forceinline__ void mma8(float* c,
    uint32_t a0, uint32_t a1, uint32_t a2, uint32_t a3,
    uint32_t b0, uint32_t b1)
{
    asm volatile(
        "mma.sync.aligned.m16n8k8.row.col.f32.tf32.tf32.f32 "
        "{%0,%1,%2,%3}, {%4,%5,%6,%7}, {%8,%9}, {%0,%1,%2,%3};"
        : "+f"(c[0]), "+f"(c[1]), "+f"(c[2]), "+f"(c[3])
        : "r"(a0), "r"(a1), "r"(a2), "r"(a3), "r"(b0), "r"(b1));
}

__device__ __forceinline__ float gelu_exact(float h) {
    return 0.5f * h * (1.0f + erff(h * 0.70710678118654752f));
}

// ---------------------------------------------------------------- misc kernels
__global__ void k_init_affine() { g_al[threadIdx.x] = 1.0f; g_bt[threadIdx.x] = 0.0f; }

// ---------------- attention pass 1: compute o_re/o_im, store TRANSPOSED ----
__global__ __launch_bounds__(256) void k_attn_pre(
    const float* __restrict__ act, float* __restrict__ Pre, float* __restrict__ Pim)
{
    __shared__ float sre[32][33];
    __shared__ float sim[32][33];
    const int c0 = blockIdx.x * 32;
    const int d0 = blockIdx.y * 32;
    const int b  = blockIdx.z;
    const int tx = threadIdx.x & 31;
    const int ty = threadIdx.x >> 5;

    const int d2 = d0 + tx;
    const int d3 = (DM - 1) - d2;
    const float al2 = g_al[d2], bt2 = g_bt[d2];
    const float al3 = g_al[d3], bt3 = g_bt[d3];

    #pragma unroll
    for (int rr = 0; rr < 4; rr++) {
        int c2l = ty + rr * 8;
        int c2 = c0 + c2l;
        if (c2 < CC) {
            int c3 = (CC - 1) - c2;
            float qr = act[((size_t)b        * CC + c2) * DM + d2] * al2 + bt2;
            float qi = act[((size_t)(64 + b) * CC + c2) * DM + d2] * al2 + bt2;
            float kr = act[((size_t)b        * CC + c3) * DM + d3] * al3 + bt3;
            float ki = act[((size_t)(64 + b) * CC + c3) * DM + d3] * al3 + bt3;
            float asr = qr * kr - qi * ki;
            float asi = qr * ki - qi * kr;
            sre[c2l][tx] = 0.25f * (asr - asi) * qr;
            sim[c2l][tx] = 0.25f * (asr + asi) * qr;
        }
    }
    __syncthreads();
    #pragma unroll
    for (int rr = 0; rr < 4; rr++) {
        int d2l = ty + rr * 8;
        int c2 = c0 + tx;
        if (c2 < CC) {
            size_t o = ((size_t)b * DM + (d0 + d2l)) * CC + c2;
            Pre[o] = sre[tx][d2l];
            Pim[o] = sim[tx][d2l];
        }
    }
}

// ---------------- attention pass 2: src = y*affine + P (fully linear) ------
__global__ void k_attn_post(
    const float* __restrict__ act, const float* __restrict__ Pre,
    const float* __restrict__ Pim, float* __restrict__ src)
{
    size_t idx = (size_t)blockIdx.x * blockDim.x + threadIdx.x;   // float4 index
    if (idx >= (size_t)EMB_M * DM / 4) return;
    size_t e = idx * 4;
    int d = (int)(e & 255);
    float4 al = *(const float4*)&g_al[d];
    float4 bt = *(const float4*)&g_bt[d];

    const float4* a4 = (const float4*)act;
    float4 a0 = a4[idx];
    float4 a1 = a4[idx + (size_t)EMB_M * DM / 4];
    float4 p0 = ((const float4*)Pre)[idx];
    float4 p1 = ((const float4*)Pim)[idx];

    float4 o0, o1;
    o0.x = a0.x * al.x + bt.x + p0.x;  o0.y = a0.y * al.y + bt.y + p0.y;
    o0.z = a0.z * al.z + bt.z + p0.z;  o0.w = a0.w * al.w + bt.w + p0.w;
    o1.x = a1.x * al.x + bt.x + p1.x;  o1.y = a1.y * al.y + bt.y + p1.y;
    o1.z = a1.z * al.z + bt.z + p1.z;  o1.w = a1.w * al.w + bt.w + p1.w;

    ((float4*)src)[idx] = o0;
    ((float4*)src)[idx + (size_t)EMB_M * DM / 4] = o1;
}

__global__ void k_stats(const float* __restrict__ buf)
{
    int ch = threadIdx.x;
    int blk = blockIdx.x;
    float s = 0.0f, q = 0.0f;
    size_t row0 = (size_t)blk * ROWS_PER_STATB;
    #pragma unroll 8
    for (int i = 0; i < ROWS_PER_STATB; i++) {
        float v = buf[(row0 + i) * DM + ch];
        s += v; q += v * v;
    }
    g_psum[blk * DM + ch] = s;
    g_psq [blk * DM + ch] = q;
}

__global__ void k_finalize(const float* __restrict__ gamma, const float* __restrict__ beta)
{
    int ch = threadIdx.x;
    float s = 0.0f, q = 0.0f;
    for (int i = 0; i < NSTATB; i++) { s += g_psum[i * DM + ch]; q += g_psq[i * DM + ch]; }
    const float inv = 1.0f / (float)MROWS;
    float m = s * inv;
    float v = q * inv - m * m;
    float al = gamma[ch] * rsqrtf(v + EPSV);
    g_al[ch] = al;
    g_bt[ch] = beta[ch] - m * al;
}

__global__ void k_out(const float* __restrict__ act, float* __restrict__ out)
{
    size_t e = (size_t)blockIdx.x * blockDim.x + threadIdx.x;
    if (e >= (size_t)BB * CC * DM) return;
    int d = (int)(e & 255);
    size_t r = e >> 8;
    float al = g_al[d], bt = g_bt[d];
    float v0 = act[r * DM + d] * al + bt;
    float v1 = act[((size_t)EMB_M + r) * DM + d] * al + bt;
    *(float2*)&out[2 * e] = make_float2(v0, v1);
}

// ---------------------------------------------------------------- ff GEMMs (tf32 mma)
// MODE 0: ff1 : out[M,512] = gelu( (src*al+bt)[M,256] @ W1^T + b1 )
// MODE 1: ff2 : out[M,256] = ff[M,512] @ W2^T + b2 + (src*al+bt)
// CTA tile 128x128, 128 threads = 4 warps (2M x 2N), warp tile 64x64.
// BK=16, double-buffered static smem, one barrier per chunk.
template<int MODE>
__global__ __launch_bounds__(128) void k_ffgemm(
    const float* __restrict__ A,  const float* __restrict__ Bm,
    const float* __restrict__ bias, const float* __restrict__ src,
    float* __restrict__ out)
{
    constexpr int KK   = (MODE == 0) ? DM : DFF;
    constexpr int NKB  = KK / 16;
    constexpr int ASTR = KK;
    constexpr int OSTR = (MODE == 0) ? DFF : DM;

    __shared__ uint32_t sA[2][2][128][8];
    __shared__ uint32_t sB[2][2][128][8];

    const int tid  = threadIdx.x;
    const int lane = tid & 31;
    const int w    = tid >> 5;
    const int wm   = w & 1;      // 0..1  (M)
    const int wn   = w >> 1;     // 0..1  (N)
    const int m0   = blockIdx.y * 128;
    const int n0   = blockIdx.x * 128;
    const int g    = lane >> 2;  // 0..7
    const int tg   = lane & 3;   // 0..3

    float acc[4][8][4];
    #pragma unroll
    for (int mt = 0; mt < 4; mt++)
        #pragma unroll
        for (int nt = 0; nt < 8; nt++)
            #pragma unroll
            for (int i = 0; i < 4; i++) acc[mt][nt][i] = 0.0f;

    float4 ra[4], rb[4];   // staging: 128 rows x 16 k / 128 thr = 4 float4 each

    auto ldg = [&](int kb) {
        #pragma unroll
        for (int it = 0; it < 4; it++) {
            int idx = it * 128 + tid;
            int row = idx >> 2, kq = idx & 3;
            int kg = kb * 16 + kq * 4;
            ra[it] = *(const float4*)&A [(size_t)(m0 + row) * ASTR + kg];
            rb[it] = *(const float4*)&Bm[(size_t)(n0 + row) * ASTR + kg];
            if (MODE == 0) {
                float4 al = *(const float4*)&g_al[kg];
                float4 bt = *(const float4*)&g_bt[kg];
                ra[it].x = ra[it].x * al.x + bt.x;
                ra[it].y = ra[it].y * al.y + bt.y;
                ra[it].z = ra[it].z * al.z + bt.z;
                ra[it].w = ra[it].w * al.w + bt.w;
            }
        }
    };

    auto sts = [&](int buf) {
        #pragma unroll
        for (int it = 0; it < 4; it++) {
            int idx = it * 128 + tid;
            int row = idx >> 2, kq = idx & 3;
            int panel = kq >> 1, par = kq & 1;
            sA[buf][panel][row][0 + par] = f2tf32(ra[it].x);
            sA[buf][panel][row][2 + par] = f2tf32(ra[it].y);
            sA[buf][panel][row][4 + par] = f2tf32(ra[it].z);
            sA[buf][panel][row][6 + par] = f2tf32(ra[it].w);
            sB[buf][panel][row][0 + par] = f2tf32(rb[it].x);
            sB[buf][panel][row][2 + par] = f2tf32(rb[it].y);
            sB[buf][panel][row][4 + par] = f2tf32(rb[it].z);
            sB[buf][panel][row][6 + par] = f2tf32(rb[it].w);
        }
    };

    auto compute = [&](int buf) {
        #pragma unroll
        for (int p = 0; p < 2; p++) {
            uint32_t af[4][4];
            #pragma unroll
            for (int mt = 0; mt < 4; mt++) {
                int r = wm * 64 + mt * 16 + g;
                uint2 lo = *(const uint2*)&sA[buf][p][r][tg * 2];
                uint2 hi = *(const uint2*)&sA[buf][p][r + 8][tg * 2];
                af[mt][0] = lo.x; af[mt][2] = lo.y;
                af[mt][1] = hi.x; af[mt][3] = hi.y;
            }
            uint2 bf[8];
            #pragma unroll
            for (int nt = 0; nt < 8; nt++) {
                int n = wn * 64 + nt * 8 + g;
                bf[nt] = *(const uint2*)&sB[buf][p][n][tg * 2];
            }
            #pragma unroll
            for (int mt = 0; mt < 4; mt++)
                #pragma unroll
                for (int nt = 0; nt < 8; nt++)
                    mma8(acc[mt][nt], af[mt][0], af[mt][1], af[mt][2], af[mt][3],
                         bf[nt].x, bf[nt].y);
        }
    };

    ldg(0); sts(0);
    __syncthreads();
    #pragma unroll 1
    for (int kb = 0; kb < NKB; kb++) {
        int cur = kb & 1;
        if (kb + 1 < NKB) ldg(kb + 1);
        compute(cur);
        if (kb + 1 < NKB) sts(cur ^ 1);
        __syncthreads();
    }

    // ---- epilogue
    #pragma unroll
    for (int mt = 0; mt < 4; mt++) {
        int r0 = m0 + wm * 64 + mt * 16 + g;
        int r1 = r0 + 8;
        #pragma unroll
        for (int nt = 0; nt < 8; nt++) {
            int cb = n0 + wn * 64 + nt * 8 + tg * 2;
            float* c = acc[mt][nt];
            float2 bi = *(const float2*)&bias[cb];
            if (MODE == 0) {
                float2 o0 = make_float2(gelu_exact(c[0] + bi.x), gelu_exact(c[1] + bi.y));
                float2 o1 = make_float2(gelu_exact(c[2] + bi.x), gelu_exact(c[3] + bi.y));
                *(float2*)&out[(size_t)r0 * OSTR + cb] = o0;
                *(float2*)&out[(size_t)r1 * OSTR + cb] = o1;
            } else {
                float2 al = *(const float2*)&g_al[cb];
                float2 bt = *(const float2*)&g_bt[cb];
                float2 s0 = *(const float2*)&src[(size_t)r0 * DM + cb];
                float2 s1 = *(const float2*)&src[(size_t)r1 * DM + cb];
                float2 o0 = make_float2(c[0] + bi.x + s0.x * al.x + bt.x,
                                        c[1] + bi.y + s0.y * al.y + bt.y);
                float2 o1 = make_float2(c[2] + bi.x + s1.x * al.x + bt.x,
                                        c[3] + bi.y + s1.y * al.y + bt.y);
                *(float2*)&out[(size_t)r0 * OSTR + cb] = o0;
                *(float2*)&out[(size_t)r1 * OSTR + cb] = o1;
            }
        }
    }
}

// ---------------------------------------------------------------- embedding GEMM (proven R3 path)
__global__ __launch_bounds__(256) void k_embed(
    float* __restrict__ out,
    const float* __restrict__ xre, const float* __restrict__ xim,
    const float* __restrict__ Wre, const float* __restrict__ Wim,
    const float* __restrict__ bre, const float* __restrict__ bim)
{
    constexpr int NKB = 33;   // 528 / 16

    __shared__ uint32_t sA[2][2][128][8];
    __shared__ uint32_t sB[2][2][128][8];

    const int tid  = threadIdx.x;
    const int lane = tid & 31;
    const int w    = tid >> 5;
    const int wm   = w & 1;
    const int wn   = w >> 1;
    const int m0   = blockIdx.y * 128;
    const int n0   = blockIdx.x * 128;
    const int g    = lane >> 2;
    const int tg   = lane & 3;

    const int which = blockIdx.z;
    const float* W0  = which ? Wim : Wre;
    const float* W1p = which ? Wre : Wim;
    const float  sgn = which ? 1.0f : -1.0f;

    float acc[4][4][4];
    #pragma unroll
    for (int mt = 0; mt < 4; mt++)
        #pragma unroll
        for (int nt = 0; nt < 4; nt++)
            #pragma unroll
            for (int i = 0; i < 4; i++) acc[mt][nt][i] = 0.0f;

    float ea[8], eb[8];

    auto ldg = [&](int kb) {
        #pragma unroll
        for (int it = 0; it < 8; it++) {
            int idx = it * 256 + tid;
            int row = idx >> 4, kl = idx & 15;
            int kg = kb * 16 + kl;
            float a = 0.0f, b = 0.0f;
            if (kg < FBINS) {
                a = xre[(size_t)(m0 + row) * FBINS + kg];
                b = W0 [(size_t)(n0 + row) * FBINS + kg];
            } else if (kg < 2 * FBINS) {
                a = xim[(size_t)(m0 + row) * FBINS + (kg - FBINS)];
                b = sgn * W1p[(size_t)(n0 + row) * FBINS + (kg - FBINS)];
            }
            ea[it] = a; eb[it] = b;
        }
    };

    auto sts = [&](int buf) {
        #pragma unroll
        for (int it = 0; it < 8; it++) {
            int idx = it * 256 + tid;
            int row = idx >> 4, kl = idx & 15;
            int panel = kl >> 3, kk = kl & 7;
            int col = (kk & 3) * 2 + (kk >> 2);
            sA[buf][panel][row][col] = f2tf32(ea[it]);
            sB[buf][panel][row][col] = f2tf32(eb[it]);
        }
    };

    auto compute = [&](int buf) {
        #pragma unroll
        for (int p = 0; p < 2; p++) {
            uint32_t af[4][4];
            #pragma unroll
            for (int mt = 0; mt < 4; mt++) {
                int r = wm * 64 + mt * 16 + g;
                uint2 lo = *(const uint2*)&sA[buf][p][r][tg * 2];
                uint2 hi = *(const uint2*)&sA[buf][p][r + 8][tg * 2];
                af[mt][0] = lo.x; af[mt][2] = lo.y;
                af[mt][1] = hi.x; af[mt][3] = hi.y;
            }
            #pragma unroll
            for (int nt = 0; nt < 4; nt++) {
                int n = wn * 32 + nt * 8 + g;
                uint2 bb = *(const uint2*)&sB[buf][p][n][tg * 2];
                #pragma unroll
                for (int mt = 0; mt < 4; mt++)
                    mma8(acc[mt][nt], af[mt][0], af[mt][1], af[mt][2], af[mt][3],
                         bb.x, bb.y);
            }
        }
    };

    ldg(0); sts(0);
    __syncthreads();
    #pragma unroll 1
    for (int kb = 0; kb < NKB; kb++) {
        int cur = kb & 1;
        if (kb + 1 < NKB) ldg(kb + 1);
        compute(cur);
        if (kb + 1 < NKB) sts(cur ^ 1);
        __syncthreads();
    }

    const float* biasp = which ? bim : bre;
    float* outp = out + (size_t)which * EMB_M * DM;

    #pragma unroll
    for (int mt = 0; mt < 4; mt++) {
        int r0 = m0 + wm * 64 + mt * 16 + g;
        int r1 = r0 + 8;
        #pragma unroll
        for (int nt = 0; nt < 4; nt++) {
            int cb = n0 + wn * 32 + nt * 8 + tg * 2;
            float* c = acc[mt][nt];
            float2 bi = *(const float2*)&biasp[cb];
            float2 o0 = make_float2(c[0] + bi.x, c[1] + bi.y);
            float2 o1 = make_float2(c[2] + bi.x, c[3] + bi.y);
            *(float2*)&outp[(size_t)r0 * DM + cb] = o0;
            *(float2*)&outp[(size_t)r1 * DM + cb] = o1;
        }
    }
}

// ---------------------------------------------------------------- launch
extern "C" void kernel_launch(void* const* d_in, const int* in_sizes, int n_in,
                              void* d_out, int out_size)
{
    const float* x_re   = (const float*)d_in[0];
    const float* x_im   = (const float*)d_in[1];
    const float* embWre = (const float*)d_in[2];
    const float* embWim = (const float*)d_in[3];
    const float* embbre = (const float*)d_in[4];
    const float* embbim = (const float*)d_in[5];
    const float* W1     = (const float*)d_in[6];
    const float* b1     = (const float*)d_in[7];
    const float* W2     = (const float*)d_in[8];
    const float* b2     = (const float*)d_in[9];
    const float* gamma1 = (const float*)d_in[10];
    const float* beta1  = (const float*)d_in[11];
    const float* gamma2 = (const float*)d_in[12];
    const float* beta2  = (const float*)d_in[13];
    float* out = (float*)d_out;

    float* act = nullptr; float* src = nullptr; float* ff = nullptr;
    cudaGetSymbolAddress((void**)&act, g_act);
    cudaGetSymbolAddress((void**)&src, g_src);
    cudaGetSymbolAddress((void**)&ff,  g_ff);

    k_init_affine<<<1, DM>>>();

    {
        dim3 grid(2, EMB_M / 128, 2);
        k_embed<<<grid, 256>>>(act, x_re, x_im, embWre, embWim, embbre, embbim);
    }

    float* Pre = ff;
    float* Pim = ff + (size_t)EMB_M * DM;

    const int post_blocks = (int)(((size_t)EMB_M * DM / 4 + 255) / 256);

    for (int l = 0; l < NL; l++) {
        const float* W1l = W1 + (size_t)l * DFF * DM;
        const float* b1l = b1 + (size_t)l * DFF;
        const float* W2l = W2 + (size_t)l * DM * DFF;
        const float* b2l = b2 + (size_t)l * DM;

        {
            dim3 gpre((CC + 31) / 32, DM / 32, BB);
            k_attn_pre<<<gpre, 256>>>(act, Pre, Pim);
            k_attn_post<<<post_blocks, 256>>>(act, Pre, Pim, src);
        }

        k_stats<<<NSTATB, DM>>>(src);
        k_finalize<<<1, DM>>>(gamma1 + l * DM, beta1 + l * DM);

        {
            dim3 g1(DFF / 128, MROWS / 128);
            k_ffgemm<0><<<g1, 128>>>(src, W1l, b1l, nullptr, ff);
            dim3 g2(DM / 128, MROWS / 128);
            k_ffgemm<1><<<g2, 128>>>(ff, W2l, b2l, src, act);
        }

        k_stats<<<NSTATB, DM>>>(act);
        k_finalize<<<1, DM>>>(gamma2 + l * DM, beta2 + l * DM);
    }

    const size_t NO = (size_t)BB * CC * DM;
    k_out<<<(int)((NO + 255) / 256), 256>>>(act, out);
}

// round 6
// speedup vs baseline: 2.9934x; 1.1357x over previous
#include <cuda_runtime.h>
#include <math.h>
#include <stdint.h>

// ---------------------------------------------------------------- shapes
#define BB      64
#define CC      862
#define FBINS   257
#define DM      256
#define DFF     512
#define NL      3
#define EPSV    1e-5f

#define EMB_M   (BB*CC)                 // 55168
#define MROWS   (2*BB*CC)               // 110336
#define NSTATB  431
#define ROWS_PER_STATB 256              // 431*256 = 110336

// ---------------------------------------------------------------- scratch
__device__ float g_act[(size_t)MROWS * DM];
__device__ float g_src[(size_t)MROWS * DM];
__device__ float g_ff [(size_t)MROWS * DFF];   // also reused as P_re/P_im during attn
__device__ float g_psum[NSTATB * DM];
__device__ float g_psq [NSTATB * DM];
__device__ float g_al[DM];
__device__ float g_bt[DM];
__device__ float g_w1m[DFF * DM];              // W1 with BN1 affine folded
__device__ float g_b1m[DFF];

// ---------------------------------------------------------------- helpers
__device__ __forceinline__ uint32_t f2tf32(float x) {
    uint32_t r;
    asm("cvt.rna.tf32.f32 %0, %1;" : "=r"(r) : "f"(x));
    return r;
}

__device__ __forceinline__ uint32_t smem_u32(const void* p) {
    uint32_t a;
    asm("{ .reg .u64 t; cvta.to.shared.u64 t, %1; cvt.u32.u64 %0, t; }" : "=r"(a) : "l"(p));
    return a;
}

__device__ __forceinline__ void cp16(uint32_t dst, const void* src) {
    asm volatile("cp.async.cg.shared.global [%0], [%1], 16;" :: "r"(dst), "l"(src));
}
#define CP_COMMIT() asm volatile("cp.async.commit_group;" ::: "memory")
#define CP_WAIT2()  asm volatile("cp.async.wait_group 2;" ::: "memory")

__device__ __forceinline__ void mma8(float* c,
    uint32_t a0, uint32_t a1, uint32_t a2, uint32_t a3,
    uint32_t b0, uint32_t b1)
{
    asm volatile(
        "mma.sync.aligned.m16n8k8.row.col.f32.tf32.tf32.f32 "
        "{%0,%1,%2,%3}, {%4,%5,%6,%7}, {%8,%9}, {%0,%1,%2,%3};"
        : "+f"(c[0]), "+f"(c[1]), "+f"(c[2]), "+f"(c[3])
        : "r"(a0), "r"(a1), "r"(a2), "r"(a3), "r"(b0), "r"(b1));
}

__device__ __forceinline__ float gelu_exact(float h) {
    return 0.5f * h * (1.0f + erff(h * 0.70710678118654752f));
}

// ---------------------------------------------------------------- misc kernels
__global__ void k_init_affine() { g_al[threadIdx.x] = 1.0f; g_bt[threadIdx.x] = 0.0f; }

// ---------------- attention pass 1: compute o_re/o_im, store TRANSPOSED ----
__global__ __launch_bounds__(256) void k_attn_pre(
    const float* __restrict__ act, float* __restrict__ Pre, float* __restrict__ Pim)
{
    __shared__ float sre[32][33];
    __shared__ float sim[32][33];
    const int c0 = blockIdx.x * 32;
    const int d0 = blockIdx.y * 32;
    const int b  = blockIdx.z;
    const int tx = threadIdx.x & 31;
    const int ty = threadIdx.x >> 5;

    const int d2 = d0 + tx;
    const int d3 = (DM - 1) - d2;
    const float al2 = g_al[d2], bt2 = g_bt[d2];
    const float al3 = g_al[d3], bt3 = g_bt[d3];

    #pragma unroll
    for (int rr = 0; rr < 4; rr++) {
        int c2l = ty + rr * 8;
        int c2 = c0 + c2l;
        if (c2 < CC) {
            int c3 = (CC - 1) - c2;
            float qr = act[((size_t)b        * CC + c2) * DM + d2] * al2 + bt2;
            float qi = act[((size_t)(64 + b) * CC + c2) * DM + d2] * al2 + bt2;
            float kr = act[((size_t)b        * CC + c3) * DM + d3] * al3 + bt3;
            float ki = act[((size_t)(64 + b) * CC + c3) * DM + d3] * al3 + bt3;
            float asr = qr * kr - qi * ki;
            float asi = qr * ki - qi * kr;
            sre[c2l][tx] = 0.25f * (asr - asi) * qr;
            sim[c2l][tx] = 0.25f * (asr + asi) * qr;
        }
    }
    __syncthreads();
    #pragma unroll
    for (int rr = 0; rr < 4; rr++) {
        int d2l = ty + rr * 8;
        int c2 = c0 + tx;
        if (c2 < CC) {
            size_t o = ((size_t)b * DM + (d0 + d2l)) * CC + c2;
            Pre[o] = sre[tx][d2l];
            Pim[o] = sim[tx][d2l];
        }
    }
}

// ---------------- attention pass 2: src = y*affine + P (fully linear) ------
__global__ void k_attn_post(
    const float* __restrict__ act, const float* __restrict__ Pre,
    const float* __restrict__ Pim, float* __restrict__ src)
{
    size_t idx = (size_t)blockIdx.x * blockDim.x + threadIdx.x;   // float4 index
    if (idx >= (size_t)EMB_M * DM / 4) return;
    size_t e = idx * 4;
    int d = (int)(e & 255);
    float4 al = *(const float4*)&g_al[d];
    float4 bt = *(const float4*)&g_bt[d];

    const float4* a4 = (const float4*)act;
    float4 a0 = a4[idx];
    float4 a1 = a4[idx + (size_t)EMB_M * DM / 4];
    float4 p0 = ((const float4*)Pre)[idx];
    float4 p1 = ((const float4*)Pim)[idx];

    float4 o0, o1;
    o0.x = a0.x * al.x + bt.x + p0.x;  o0.y = a0.y * al.y + bt.y + p0.y;
    o0.z = a0.z * al.z + bt.z + p0.z;  o0.w = a0.w * al.w + bt.w + p0.w;
    o1.x = a1.x * al.x + bt.x + p1.x;  o1.y = a1.y * al.y + bt.y + p1.y;
    o1.z = a1.z * al.z + bt.z + p1.z;  o1.w = a1.w * al.w + bt.w + p1.w;

    ((float4*)src)[idx] = o0;
    ((float4*)src)[idx + (size_t)EMB_M * DM / 4] = o1;
}

__global__ void k_stats(const float* __restrict__ buf)
{
    int ch = threadIdx.x;
    int blk = blockIdx.x;
    float s = 0.0f, q = 0.0f;
    size_t row0 = (size_t)blk * ROWS_PER_STATB;
    #pragma unroll 8
    for (int i = 0; i < ROWS_PER_STATB; i++) {
        float v = buf[(row0 + i) * DM + ch];
        s += v; q += v * v;
    }
    g_psum[blk * DM + ch] = s;
    g_psq [blk * DM + ch] = q;
}

__global__ void k_finalize(const float* __restrict__ gamma, const float* __restrict__ beta)
{
    int ch = threadIdx.x;
    float s = 0.0f, q = 0.0f;
    for (int i = 0; i < NSTATB; i++) { s += g_psum[i * DM + ch]; q += g_psq[i * DM + ch]; }
    const float inv = 1.0f / (float)MROWS;
    float m = s * inv;
    float v = q * inv - m * m;
    float al = gamma[ch] * rsqrtf(v + EPSV);
    g_al[ch] = al;
    g_bt[ch] = beta[ch] - m * al;
}

// fold BN1 affine into W1/b1: W1'[f][d] = W1[f][d]*al[d]; b1'[f]=b1[f]+sum_d W1[f][d]*bt[d]
__global__ __launch_bounds__(256) void k_fold(const float* __restrict__ W1,
                                              const float* __restrict__ b1)
{
    __shared__ float red[256];
    int f = blockIdx.x;
    int t = threadIdx.x;
    float w = W1[(size_t)f * DM + t];
    g_w1m[(size_t)f * DM + t] = w * g_al[t];
    red[t] = w * g_bt[t];
    __syncthreads();
    #pragma unroll
    for (int s = 128; s > 0; s >>= 1) {
        if (t < s) red[t] += red[t + s];
        __syncthreads();
    }
    if (t == 0) g_b1m[f] = b1[f] + red[0];
}

__global__ void k_out(const float* __restrict__ act, float* __restrict__ out)
{
    size_t e = (size_t)blockIdx.x * blockDim.x + threadIdx.x;
    if (e >= (size_t)BB * CC * DM) return;
    int d = (int)(e & 255);
    size_t r = e >> 8;
    float al = g_al[d], bt = g_bt[d];
    float v0 = act[r * DM + d] * al + bt;
    float v1 = act[((size_t)EMB_M + r) * DM + d] * al + bt;
    *(float2*)&out[2 * e] = make_float2(v0, v1);
}

// ---------------------------------------------------------------- ff GEMMs (tf32 mma + cp.async)
// MODE 0: ff1 : out[M,512] = gelu( src[M,256] @ W1'^T + b1' )   (affine pre-folded)
// MODE 1: ff2 : out[M,256] = ff[M,512] @ W2^T + b2 + (src*al+bt)
// CTA tile 128x128, 128 threads = 4 warps (2M x 2N), warp tile 64x64.
// BK=16, 4-stage cp.async pipeline, raw fp32 in smem, cvt at fragment load.
#define RS      20                       // padded row stride (floats)
#define STG     4
#define CHUNK_F (128 * RS)               // floats per tile per stage
#define DYNSM   (STG * CHUNK_F * 4 * 2)  // bytes: A + B rings = 81920

template<int MODE>
__global__ __launch_bounds__(128) void k_ffgemm(
    const float* __restrict__ A,  const float* __restrict__ Bm,
    const float* __restrict__ bias, const float* __restrict__ src,
    float* __restrict__ out)
{
    constexpr int KK   = (MODE == 0) ? DM : DFF;
    constexpr int NKB  = KK / 16;
    constexpr int ASTR = KK;
    constexpr int OSTR = (MODE == 0) ? DFF : DM;

    extern __shared__ float dyn[];
    float* pA = dyn;                    // [STG][128][RS]
    float* pB = dyn + STG * CHUNK_F;

    const int tid  = threadIdx.x;
    const int lane = tid & 31;
    const int w    = tid >> 5;
    const int wm   = w & 1;      // 0..1  (M)
    const int wn   = w >> 1;     // 0..1  (N)
    const int m0   = blockIdx.y * 128;
    const int n0   = blockIdx.x * 128;
    const int g    = lane >> 2;  // 0..7
    const int tg   = lane & 3;   // 0..3

    const uint32_t baseA = smem_u32(pA);
    const uint32_t baseB = smem_u32(pB);

    float acc[4][8][4];
    #pragma unroll
    for (int mt = 0; mt < 4; mt++)
        #pragma unroll
        for (int nt = 0; nt < 8; nt++)
            #pragma unroll
            for (int i = 0; i < 4; i++) acc[mt][nt][i] = 0.0f;

    const int srow = tid >> 2, skq = tid & 3;   // 32 rows per it-step, 4 quads

    auto issue = [&](int kb, int s) {
        uint32_t dA = baseA + (uint32_t)s * CHUNK_F * 4;
        uint32_t dB = baseB + (uint32_t)s * CHUNK_F * 4;
        #pragma unroll
        for (int it = 0; it < 4; it++) {
            int row = it * 32 + srow;
            int kg  = kb * 16 + skq * 4;
            cp16(dA + row * (RS * 4) + skq * 16, &A [(size_t)(m0 + row) * ASTR + kg]);
            cp16(dB + row * (RS * 4) + skq * 16, &Bm[(size_t)(n0 + row) * ASTR + kg]);
        }
    };

    auto compute = [&](int s) {
        const float* cA = pA + s * CHUNK_F;
        const float* cB = pB + s * CHUNK_F;
        #pragma unroll
        for (int p = 0; p < 2; p++) {
            const int kb8 = p * 8;
            uint32_t af[4][4];
            #pragma unroll
            for (int mt = 0; mt < 4; mt++) {
                int r = wm * 64 + mt * 16 + g;
                af[mt][0] = f2tf32(cA[r       * RS + kb8 + tg]);
                af[mt][1] = f2tf32(cA[(r + 8) * RS + kb8 + tg]);
                af[mt][2] = f2tf32(cA[r       * RS + kb8 + tg + 4]);
                af[mt][3] = f2tf32(cA[(r + 8) * RS + kb8 + tg + 4]);
            }
            uint32_t bf[8][2];
            #pragma unroll
            for (int nt = 0; nt < 8; nt++) {
                int n = wn * 64 + nt * 8 + g;
                bf[nt][0] = f2tf32(cB[n * RS + kb8 + tg]);
                bf[nt][1] = f2tf32(cB[n * RS + kb8 + tg + 4]);
            }
            #pragma unroll
            for (int mt = 0; mt < 4; mt++)
                #pragma unroll
                for (int nt = 0; nt < 8; nt++)
                    mma8(acc[mt][nt], af[mt][0], af[mt][1], af[mt][2], af[mt][3],
                         bf[nt][0], bf[nt][1]);
        }
    };

    issue(0, 0); CP_COMMIT();
    issue(1, 1); CP_COMMIT();
    issue(2, 2); CP_COMMIT();

    #pragma unroll 1
    for (int kb = 0; kb < NKB; kb++) {
        CP_WAIT2();              // chunk kb's group complete (<=2 newer in flight)
        __syncthreads();         // all threads' data visible; prev compute done
        if (kb + 3 < NKB) { issue(kb + 3, (kb + 3) & 3); }
        CP_COMMIT();             // keep group accounting uniform
        compute(kb & 3);
    }

    // ---- epilogue
    #pragma unroll
    for (int mt = 0; mt < 4; mt++) {
        int r0 = m0 + wm * 64 + mt * 16 + g;
        int r1 = r0 + 8;
        #pragma unroll
        for (int nt = 0; nt < 8; nt++) {
            int cb = n0 + wn * 64 + nt * 8 + tg * 2;
            float* c = acc[mt][nt];
            float2 bi = *(const float2*)&bias[cb];
            if (MODE == 0) {
                float2 o0 = make_float2(gelu_exact(c[0] + bi.x), gelu_exact(c[1] + bi.y));
                float2 o1 = make_float2(gelu_exact(c[2] + bi.x), gelu_exact(c[3] + bi.y));
                *(float2*)&out[(size_t)r0 * OSTR + cb] = o0;
                *(float2*)&out[(size_t)r1 * OSTR + cb] = o1;
            } else {
                float2 al = *(const float2*)&g_al[cb];
                float2 bt = *(const float2*)&g_bt[cb];
                float2 s0 = *(const float2*)&src[(size_t)r0 * DM + cb];
                float2 s1 = *(const float2*)&src[(size_t)r1 * DM + cb];
                float2 o0 = make_float2(c[0] + bi.x + s0.x * al.x + bt.x,
                                        c[1] + bi.y + s0.y * al.y + bt.y);
                float2 o1 = make_float2(c[2] + bi.x + s1.x * al.x + bt.x,
                                        c[3] + bi.y + s1.y * al.y + bt.y);
                *(float2*)&out[(size_t)r0 * OSTR + cb] = o0;
                *(float2*)&out[(size_t)r1 * OSTR + cb] = o1;
            }
        }
    }
}

// ---------------------------------------------------------------- embedding GEMM (proven R3 path)
__global__ __launch_bounds__(256) void k_embed(
    float* __restrict__ out,
    const float* __restrict__ xre, const float* __restrict__ xim,
    const float* __restrict__ Wre, const float* __restrict__ Wim,
    const float* __restrict__ bre, const float* __restrict__ bim)
{
    constexpr int NKB = 33;   // 528 / 16

    __shared__ uint32_t sA[2][2][128][8];
    __shared__ uint32_t sB[2][2][128][8];

    const int tid  = threadIdx.x;
    const int lane = tid & 31;
    const int w    = tid >> 5;
    const int wm   = w & 1;
    const int wn   = w >> 1;
    const int m0   = blockIdx.y * 128;
    const int n0   = blockIdx.x * 128;
    const int g    = lane >> 2;
    const int tg   = lane & 3;

    const int which = blockIdx.z;
    const float* W0  = which ? Wim : Wre;
    const float* W1p = which ? Wre : Wim;
    const float  sgn = which ? 1.0f : -1.0f;

    float acc[4][4][4];
    #pragma unroll
    for (int mt = 0; mt < 4; mt++)
        #pragma unroll
        for (int nt = 0; nt < 4; nt++)
            #pragma unroll
            for (int i = 0; i < 4; i++) acc[mt][nt][i] = 0.0f;

    float ea[8], eb[8];

    auto ldg = [&](int kb) {
        #pragma unroll
        for (int it = 0; it < 8; it++) {
            int idx = it * 256 + tid;
            int row = idx >> 4, kl = idx & 15;
            int kg = kb * 16 + kl;
            float a = 0.0f, b = 0.0f;
            if (kg < FBINS) {
                a = xre[(size_t)(m0 + row) * FBINS + kg];
                b = W0 [(size_t)(n0 + row) * FBINS + kg];
            } else if (kg < 2 * FBINS) {
                a = xim[(size_t)(m0 + row) * FBINS + (kg - FBINS)];
                b = sgn * W1p[(size_t)(n0 + row) * FBINS + (kg - FBINS)];
            }
            ea[it] = a; eb[it] = b;
        }
    };

    auto sts = [&](int buf) {
        #pragma unroll
        for (int it = 0; it < 8; it++) {
            int idx = it * 256 + tid;
            int row = idx >> 4, kl = idx & 15;
            int panel = kl >> 3, kk = kl & 7;
            int col = (kk & 3) * 2 + (kk >> 2);
            sA[buf][panel][row][col] = f2tf32(ea[it]);
            sB[buf][panel][row][col] = f2tf32(eb[it]);
        }
    };

    auto compute = [&](int buf) {
        #pragma unroll
        for (int p = 0; p < 2; p++) {
            uint32_t af[4][4];
            #pragma unroll
            for (int mt = 0; mt < 4; mt++) {
                int r = wm * 64 + mt * 16 + g;
                uint2 lo = *(const uint2*)&sA[buf][p][r][tg * 2];
                uint2 hi = *(const uint2*)&sA[buf][p][r + 8][tg * 2];
                af[mt][0] = lo.x; af[mt][2] = lo.y;
                af[mt][1] = hi.x; af[mt][3] = hi.y;
            }
            #pragma unroll
            for (int nt = 0; nt < 4; nt++) {
                int n = wn * 32 + nt * 8 + g;
                uint2 bb = *(const uint2*)&sB[buf][p][n][tg * 2];
                #pragma unroll
                for (int mt = 0; mt < 4; mt++)
                    mma8(acc[mt][nt], af[mt][0], af[mt][1], af[mt][2], af[mt][3],
                         bb.x, bb.y);
            }
        }
    };

    ldg(0); sts(0);
    __syncthreads();
    #pragma unroll 1
    for (int kb = 0; kb < NKB; kb++) {
        int cur = kb & 1;
        if (kb + 1 < NKB) ldg(kb + 1);
        compute(cur);
        if (kb + 1 < NKB) sts(cur ^ 1);
        __syncthreads();
    }

    const float* biasp = which ? bim : bre;
    float* outp = out + (size_t)which * EMB_M * DM;

    #pragma unroll
    for (int mt = 0; mt < 4; mt++) {
        int r0 = m0 + wm * 64 + mt * 16 + g;
        int r1 = r0 + 8;
        #pragma unroll
        for (int nt = 0; nt < 4; nt++) {
            int cb = n0 + wn * 32 + nt * 8 + tg * 2;
            float* c = acc[mt][nt];
            float2 bi = *(const float2*)&biasp[cb];
            float2 o0 = make_float2(c[0] + bi.x, c[1] + bi.y);
            float2 o1 = make_float2(c[2] + bi.x, c[3] + bi.y);
            *(float2*)&outp[(size_t)r0 * DM + cb] = o0;
            *(float2*)&outp[(size_t)r1 * DM + cb] = o1;
        }
    }
}

// ---------------------------------------------------------------- launch
extern "C" void kernel_launch(void* const* d_in, const int* in_sizes, int n_in,
                              void* d_out, int out_size)
{
    const float* x_re   = (const float*)d_in[0];
    const float* x_im   = (const float*)d_in[1];
    const float* embWre = (const float*)d_in[2];
    const float* embWim = (const float*)d_in[3];
    const float* embbre = (const float*)d_in[4];
    const float* embbim = (const float*)d_in[5];
    const float* W1     = (const float*)d_in[6];
    const float* b1     = (const float*)d_in[7];
    const float* W2     = (const float*)d_in[8];
    const float* b2     = (const float*)d_in[9];
    const float* gamma1 = (const float*)d_in[10];
    const float* beta1  = (const float*)d_in[11];
    const float* gamma2 = (const float*)d_in[12];
    const float* beta2  = (const float*)d_in[13];
    float* out = (float*)d_out;

    float* act = nullptr; float* src = nullptr; float* ff = nullptr;
    float* w1m = nullptr; float* b1m = nullptr;
    cudaGetSymbolAddress((void**)&act, g_act);
    cudaGetSymbolAddress((void**)&src, g_src);
    cudaGetSymbolAddress((void**)&ff,  g_ff);
    cudaGetSymbolAddress((void**)&w1m, g_w1m);
    cudaGetSymbolAddress((void**)&b1m, g_b1m);

    cudaFuncSetAttribute(k_ffgemm<0>, cudaFuncAttributeMaxDynamicSharedMemorySize, DYNSM);
    cudaFuncSetAttribute(k_ffgemm<1>, cudaFuncAttributeMaxDynamicSharedMemorySize, DYNSM);

    k_init_affine<<<1, DM>>>();

    {
        dim3 grid(2, EMB_M / 128, 2);
        k_embed<<<grid, 256>>>(act, x_re, x_im, embWre, embWim, embbre, embbim);
    }

    float* Pre = ff;
    float* Pim = ff + (size_t)EMB_M * DM;

    const int post_blocks = (int)(((size_t)EMB_M * DM / 4 + 255) / 256);

    for (int l = 0; l < NL; l++) {
        const float* W1l = W1 + (size_t)l * DFF * DM;
        const float* b1l = b1 + (size_t)l * DFF;
        const float* W2l = W2 + (size_t)l * DM * DFF;
        const float* b2l = b2 + (size_t)l * DM;

        {
            dim3 gpre((CC + 31) / 32, DM / 32, BB);
            k_attn_pre<<<gpre, 256>>>(act, Pre, Pim);
            k_attn_post<<<post_blocks, 256>>>(act, Pre, Pim, src);
        }

        k_stats<<<NSTATB, DM>>>(src);
        k_finalize<<<1, DM>>>(gamma1 + l * DM, beta1 + l * DM);
        k_fold<<<DFF, DM>>>(W1l, b1l);

        {
            dim3 g1(DFF / 128, MROWS / 128);
            k_ffgemm<0><<<g1, 128, DYNSM>>>(src, w1m, b1m, nullptr, ff);
            dim3 g2(DM / 128, MROWS / 128);
            k_ffgemm<1><<<g2, 128, DYNSM>>>(ff, W2l, b2l, src, act);
        }

        k_stats<<<NSTATB, DM>>>(act);
        k_finalize<<<1, DM>>>(gamma2 + l * DM, beta2 + l * DM);
    }

    const size_t NO = (size_t)BB * CC * DM;
    k_out<<<(int)((NO + 255) / 256), 256>>>(act, out);
}

// round 7
// speedup vs baseline: 3.0947x; 1.0338x over previous
#include <cuda_runtime.h>
#include <math.h>
#include <stdint.h>

// ---------------------------------------------------------------- shapes
#define BB      64
#define CC      862
#define FBINS   257
#define DM      256
#define DFF     512
#define NL      3
#define EPSV    1e-5f

#define EMB_M   (BB*CC)                 // 55168
#define MROWS   (2*BB*CC)               // 110336
#define NSTATB  431
#define ROWS_PER_STATB 256              // 431*256 = 110336

// ---------------------------------------------------------------- scratch
__device__ float g_act[(size_t)MROWS * DM];
__device__ float g_src[(size_t)MROWS * DM];
__device__ float g_ff [(size_t)MROWS * DFF];   // also reused as P_re/P_im during attn
__device__ float g_psum[NSTATB * DM];
__device__ float g_psq [NSTATB * DM];
__device__ float g_al[DM];
__device__ float g_bt[DM];
__device__ float g_w1m[DFF * DM];              // W1 * BN1-affine, tf32-rounded
__device__ float g_b1m[DFF];
__device__ float g_w2m[DM * DFF];              // W2, tf32-rounded

// ---------------------------------------------------------------- helpers
__device__ __forceinline__ uint32_t f2tf32(float x) {
    uint32_t r;
    asm("cvt.rna.tf32.f32 %0, %1;" : "=r"(r) : "f"(x));
    return r;
}

__device__ __forceinline__ uint32_t smem_u32(const void* p) {
    uint32_t a;
    asm("{ .reg .u64 t; cvta.to.shared.u64 t, %1; cvt.u32.u64 %0, t; }" : "=r"(a) : "l"(p));
    return a;
}

__device__ __forceinline__ void cp16(uint32_t dst, const void* src) {
    asm volatile("cp.async.cg.shared.global [%0], [%1], 16;" :: "r"(dst), "l"(src));
}
#define CP_COMMIT() asm volatile("cp.async.commit_group;" ::: "memory")
#define CP_WAIT2()  asm volatile("cp.async.wait_group 2;" ::: "memory")

__device__ __forceinline__ void ldsm4(uint32_t& r0, uint32_t& r1,
                                      uint32_t& r2, uint32_t& r3, uint32_t a) {
    asm volatile("ldmatrix.sync.aligned.m8n8.x4.shared.b16 {%0,%1,%2,%3}, [%4];"
        : "=r"(r0), "=r"(r1), "=r"(r2), "=r"(r3) : "r"(a));
}

__device__ __forceinline__ void mma8(float* c,
    uint32_t a0, uint32_t a1, uint32_t a2, uint32_t a3,
    uint32_t b0, uint32_t b1)
{
    asm volatile(
        "mma.sync.aligned.m16n8k8.row.col.f32.tf32.tf32.f32 "
        "{%0,%1,%2,%3}, {%4,%5,%6,%7}, {%8,%9}, {%0,%1,%2,%3};"
        : "+f"(c[0]), "+f"(c[1]), "+f"(c[2]), "+f"(c[3])
        : "r"(a0), "r"(a1), "r"(a2), "r"(a3), "r"(b0), "r"(b1));
}

__device__ __forceinline__ float gelu_exact(float h) {
    return 0.5f * h * (1.0f + erff(h * 0.70710678118654752f));
}

// ---------------------------------------------------------------- misc kernels
__global__ void k_init_affine() { g_al[threadIdx.x] = 1.0f; g_bt[threadIdx.x] = 0.0f; }

// ---------------- attention pass 1: compute o_re/o_im, store TRANSPOSED ----
__global__ __launch_bounds__(256) void k_attn_pre(
    const float* __restrict__ act, float* __restrict__ Pre, float* __restrict__ Pim)
{
    __shared__ float sre[32][33];
    __shared__ float sim[32][33];
    const int c0 = blockIdx.x * 32;
    const int d0 = blockIdx.y * 32;
    const int b  = blockIdx.z;
    const int tx = threadIdx.x & 31;
    const int ty = threadIdx.x >> 5;

    const int d2 = d0 + tx;
    const int d3 = (DM - 1) - d2;
    const float al2 = g_al[d2], bt2 = g_bt[d2];
    const float al3 = g_al[d3], bt3 = g_bt[d3];

    #pragma unroll
    for (int rr = 0; rr < 4; rr++) {
        int c2l = ty + rr * 8;
        int c2 = c0 + c2l;
        if (c2 < CC) {
            int c3 = (CC - 1) - c2;
            float qr = act[((size_t)b        * CC + c2) * DM + d2] * al2 + bt2;
            float qi = act[((size_t)(64 + b) * CC + c2) * DM + d2] * al2 + bt2;
            float kr = act[((size_t)b        * CC + c3) * DM + d3] * al3 + bt3;
            float ki = act[((size_t)(64 + b) * CC + c3) * DM + d3] * al3 + bt3;
            float asr = qr * kr - qi * ki;
            float asi = qr * ki - qi * kr;
            sre[c2l][tx] = 0.25f * (asr - asi) * qr;
            sim[c2l][tx] = 0.25f * (asr + asi) * qr;
        }
    }
    __syncthreads();
    #pragma unroll
    for (int rr = 0; rr < 4; rr++) {
        int d2l = ty + rr * 8;
        int c2 = c0 + tx;
        if (c2 < CC) {
            size_t o = ((size_t)b * DM + (d0 + d2l)) * CC + c2;
            Pre[o] = sre[tx][d2l];
            Pim[o] = sim[tx][d2l];
        }
    }
}

// ---------------- attention pass 2: src = y*affine + P (fully linear) ------
__global__ void k_attn_post(
    const float* __restrict__ act, const float* __restrict__ Pre,
    const float* __restrict__ Pim, float* __restrict__ src)
{
    size_t idx = (size_t)blockIdx.x * blockDim.x + threadIdx.x;   // float4 index
    if (idx >= (size_t)EMB_M * DM / 4) return;
    size_t e = idx * 4;
    int d = (int)(e & 255);
    float4 al = *(const float4*)&g_al[d];
    float4 bt = *(const float4*)&g_bt[d];

    const float4* a4 = (const float4*)act;
    float4 a0 = a4[idx];
    float4 a1 = a4[idx + (size_t)EMB_M * DM / 4];
    float4 p0 = ((const float4*)Pre)[idx];
    float4 p1 = ((const float4*)Pim)[idx];

    float4 o0, o1;
    o0.x = a0.x * al.x + bt.x + p0.x;  o0.y = a0.y * al.y + bt.y + p0.y;
    o0.z = a0.z * al.z + bt.z + p0.z;  o0.w = a0.w * al.w + bt.w + p0.w;
    o1.x = a1.x * al.x + bt.x + p1.x;  o1.y = a1.y * al.y + bt.y + p1.y;
    o1.z = a1.z * al.z + bt.z + p1.z;  o1.w = a1.w * al.w + bt.w + p1.w;

    ((float4*)src)[idx] = o0;
    ((float4*)src)[idx + (size_t)EMB_M * DM / 4] = o1;
}

__global__ void k_stats(const float* __restrict__ buf)
{
    int ch = threadIdx.x;
    int blk = blockIdx.x;
    float s = 0.0f, q = 0.0f;
    size_t row0 = (size_t)blk * ROWS_PER_STATB;
    #pragma unroll 8
    for (int i = 0; i < ROWS_PER_STATB; i++) {
        float v = buf[(row0 + i) * DM + ch];
        s += v; q += v * v;
    }
    g_psum[blk * DM + ch] = s;
    g_psq [blk * DM + ch] = q;
}

__global__ void k_finalize(const float* __restrict__ gamma, const float* __restrict__ beta)
{
    int ch = threadIdx.x;
    float s = 0.0f, q = 0.0f;
    for (int i = 0; i < NSTATB; i++) { s += g_psum[i * DM + ch]; q += g_psq[i * DM + ch]; }
    const float inv = 1.0f / (float)MROWS;
    float m = s * inv;
    float v = q * inv - m * m;
    float al = gamma[ch] * rsqrtf(v + EPSV);
    g_al[ch] = al;
    g_bt[ch] = beta[ch] - m * al;
}

// fold BN1 affine into W1/b1; store W1' pre-rounded to tf32
__global__ __launch_bounds__(256) void k_fold(const float* __restrict__ W1,
                                              const float* __restrict__ b1)
{
    __shared__ float red[256];
    int f = blockIdx.x;
    int t = threadIdx.x;
    float w = W1[(size_t)f * DM + t];
    g_w1m[(size_t)f * DM + t] = __uint_as_float(f2tf32(w * g_al[t]));
    red[t] = w * g_bt[t];
    __syncthreads();
    #pragma unroll
    for (int s = 128; s > 0; s >>= 1) {
        if (t < s) red[t] += red[t + s];
        __syncthreads();
    }
    if (t == 0) g_b1m[f] = b1[f] + red[0];
}

// tf32-round W2 layer slice into scratch
__global__ void k_roundW2(const float* __restrict__ W2)
{
    int i = blockIdx.x * 256 + threadIdx.x;   // DM*DFF = 131072
    g_w2m[i] = __uint_as_float(f2tf32(W2[i]));
}

__global__ void k_out(const float* __restrict__ act, float* __restrict__ out)
{
    size_t e = (size_t)blockIdx.x * blockDim.x + threadIdx.x;
    if (e >= (size_t)BB * CC * DM) return;
    int d = (int)(e & 255);
    size_t r = e >> 8;
    float al = g_al[d], bt = g_bt[d];
    float v0 = act[r * DM + d] * al + bt;
    float v1 = act[((size_t)EMB_M + r) * DM + d] * al + bt;
    *(float2*)&out[2 * e] = make_float2(v0, v1);
}

// ---------------------------------------------------------------- ff GEMMs (tf32 mma + cp.async + ldmatrix)
// MODE 0: ff1 : out[M,512] = gelu( src[M,256] @ W1'^T + b1' ), out pre-rounded tf32
// MODE 1: ff2 : out[M,256] = ff[M,512] @ W2m^T + b2 + (src*al+bt)
// CTA tile 128x128, 128 threads = 4 warps (2M x 2N), warp tile 64x64.
// BK=16, 4-stage cp.async pipeline. B (and MODE1 A) are pre-rounded tf32 in
// GMEM, so fragments go smem->mma with no CVT; MODE0 A converts after ldmatrix.
#define RS      20                       // padded row stride (floats)
#define STG     4
#define CHUNK_F (128 * RS)               // floats per tile per stage
#define CHUNK_B (CHUNK_F * 4)            // bytes per tile per stage
#define DYNSM   (STG * CHUNK_B * 2)      // A + B rings = 81920 bytes

template<int MODE>
__global__ __launch_bounds__(128) void k_ffgemm(
    const float* __restrict__ A,  const float* __restrict__ Bm,
    const float* __restrict__ bias, const float* __restrict__ src,
    float* __restrict__ out)
{
    constexpr int KK   = (MODE == 0) ? DM : DFF;
    constexpr int NKB  = KK / 16;
    constexpr int ASTR = KK;
    constexpr int OSTR = (MODE == 0) ? DFF : DM;

    extern __shared__ float dyn[];
    float* pA = dyn;                    // [STG][128][RS]
    float* pB = dyn + STG * CHUNK_F;

    const int tid  = threadIdx.x;
    const int lane = tid & 31;
    const int w    = tid >> 5;
    const int wm   = w & 1;      // 0..1  (M)
    const int wn   = w >> 1;     // 0..1  (N)
    const int m0   = blockIdx.y * 128;
    const int n0   = blockIdx.x * 128;
    const int g    = lane >> 2;  // 0..7
    const int tg   = lane & 3;   // 0..3

    const uint32_t baseA = smem_u32(pA);
    const uint32_t baseB = smem_u32(pB);

    // ldmatrix per-lane offsets (bytes) within a chunk tile
    const int q  = lane >> 3;    // 0..3 (8-lane group)
    const int lr = lane & 7;
    uint32_t offA[4], offB[4];
    #pragma unroll
    for (int mt = 0; mt < 4; mt++) {
        int row = wm * 64 + mt * 16 + lr + (q & 1) * 8;
        offA[mt] = (uint32_t)(row * RS * 4 + (q >> 1) * 16);
    }
    #pragma unroll
    for (int ntp = 0; ntp < 4; ntp++) {
        int row = wn * 64 + ntp * 16 + lr + (q >> 1) * 8;
        offB[ntp] = (uint32_t)(row * RS * 4 + (q & 1) * 16);
    }

    float acc[4][8][4];
    #pragma unroll
    for (int mt = 0; mt < 4; mt++)
        #pragma unroll
        for (int nt = 0; nt < 8; nt++)
            #pragma unroll
            for (int i = 0; i < 4; i++) acc[mt][nt][i] = 0.0f;

    const int srow = tid >> 2, skq = tid & 3;

    auto issue = [&](int kb, int s) {
        uint32_t dA = baseA + (uint32_t)s * CHUNK_B;
        uint32_t dB = baseB + (uint32_t)s * CHUNK_B;
        #pragma unroll
        for (int it = 0; it < 4; it++) {
            int row = it * 32 + srow;
            int kg  = kb * 16 + skq * 4;
            cp16(dA + row * (RS * 4) + skq * 16, &A [(size_t)(m0 + row) * ASTR + kg]);
            cp16(dB + row * (RS * 4) + skq * 16, &Bm[(size_t)(n0 + row) * ASTR + kg]);
        }
    };

    auto compute = [&](int s) {
        uint32_t cA = baseA + (uint32_t)s * CHUNK_B;
        uint32_t cB = baseB + (uint32_t)s * CHUNK_B;
        #pragma unroll
        for (int p = 0; p < 2; p++) {
            uint32_t af[4][4];
            #pragma unroll
            for (int mt = 0; mt < 4; mt++) {
                ldsm4(af[mt][0], af[mt][1], af[mt][2], af[mt][3],
                      cA + offA[mt] + p * 32);
                if (MODE == 0) {
                    af[mt][0] = f2tf32(__uint_as_float(af[mt][0]));
                    af[mt][1] = f2tf32(__uint_as_float(af[mt][1]));
                    af[mt][2] = f2tf32(__uint_as_float(af[mt][2]));
                    af[mt][3] = f2tf32(__uint_as_float(af[mt][3]));
                }
            }
            uint32_t bf[8][2];
            #pragma unroll
            for (int ntp = 0; ntp < 4; ntp++)
                ldsm4(bf[2 * ntp][0], bf[2 * ntp][1],
                      bf[2 * ntp + 1][0], bf[2 * ntp + 1][1],
                      cB + offB[ntp] + p * 32);
            #pragma unroll
            for (int mt = 0; mt < 4; mt++)
                #pragma unroll
                for (int nt = 0; nt < 8; nt++)
                    mma8(acc[mt][nt], af[mt][0], af[mt][1], af[mt][2], af[mt][3],
                         bf[nt][0], bf[nt][1]);
        }
    };

    issue(0, 0); CP_COMMIT();
    issue(1, 1); CP_COMMIT();
    issue(2, 2); CP_COMMIT();

    #pragma unroll 1
    for (int kb = 0; kb < NKB; kb++) {
        CP_WAIT2();
        __syncthreads();
        if (kb + 3 < NKB) { issue(kb + 3, (kb + 3) & 3); }
        CP_COMMIT();
        compute(kb & 3);
    }

    // ---- epilogue
    #pragma unroll
    for (int mt = 0; mt < 4; mt++) {
        int r0 = m0 + wm * 64 + mt * 16 + g;
        int r1 = r0 + 8;
        #pragma unroll
        for (int nt = 0; nt < 8; nt++) {
            int cb = n0 + wn * 64 + nt * 8 + tg * 2;
            float* c = acc[mt][nt];
            float2 bi = *(const float2*)&bias[cb];
            if (MODE == 0) {
                float2 o0, o1;
                o0.x = __uint_as_float(f2tf32(gelu_exact(c[0] + bi.x)));
                o0.y = __uint_as_float(f2tf32(gelu_exact(c[1] + bi.y)));
                o1.x = __uint_as_float(f2tf32(gelu_exact(c[2] + bi.x)));
                o1.y = __uint_as_float(f2tf32(gelu_exact(c[3] + bi.y)));
                *(float2*)&out[(size_t)r0 * OSTR + cb] = o0;
                *(float2*)&out[(size_t)r1 * OSTR + cb] = o1;
            } else {
                float2 al = *(const float2*)&g_al[cb];
                float2 bt = *(const float2*)&g_bt[cb];
                float2 s0 = *(const float2*)&src[(size_t)r0 * DM + cb];
                float2 s1 = *(const float2*)&src[(size_t)r1 * DM + cb];
                float2 o0 = make_float2(c[0] + bi.x + s0.x * al.x + bt.x,
                                        c[1] + bi.y + s0.y * al.y + bt.y);
                float2 o1 = make_float2(c[2] + bi.x + s1.x * al.x + bt.x,
                                        c[3] + bi.y + s1.y * al.y + bt.y);
                *(float2*)&out[(size_t)r0 * OSTR + cb] = o0;
                *(float2*)&out[(size_t)r1 * OSTR + cb] = o1;
            }
        }
    }
}

// ---------------------------------------------------------------- embedding GEMM (proven R3 path)
__global__ __launch_bounds__(256) void k_embed(
    float* __restrict__ out,
    const float* __restrict__ xre, const float* __restrict__ xim,
    const float* __restrict__ Wre, const float* __restrict__ Wim,
    const float* __restrict__ bre, const float* __restrict__ bim)
{
    constexpr int NKB = 33;   // 528 / 16

    __shared__ uint32_t sA[2][2][128][8];
    __shared__ uint32_t sB[2][2][128][8];

    const int tid  = threadIdx.x;
    const int lane = tid & 31;
    const int w    = tid >> 5;
    const int wm   = w & 1;
    const int wn   = w >> 1;
    const int m0   = blockIdx.y * 128;
    const int n0   = blockIdx.x * 128;
    const int g    = lane >> 2;
    const int tg   = lane & 3;

    const int which = blockIdx.z;
    const float* W0  = which ? Wim : Wre;
    const float* W1p = which ? Wre : Wim;
    const float  sgn = which ? 1.0f : -1.0f;

    float acc[4][4][4];
    #pragma unroll
    for (int mt = 0; mt < 4; mt++)
        #pragma unroll
        for (int nt = 0; nt < 4; nt++)
            #pragma unroll
            for (int i = 0; i < 4; i++) acc[mt][nt][i] = 0.0f;

    float ea[8], eb[8];

    auto ldg = [&](int kb) {
        #pragma unroll
        for (int it = 0; it < 8; it++) {
            int idx = it * 256 + tid;
            int row = idx >> 4, kl = idx & 15;
            int kg = kb * 16 + kl;
            float a = 0.0f, b = 0.0f;
            if (kg < FBINS) {
                a = xre[(size_t)(m0 + row) * FBINS + kg];
                b = W0 [(size_t)(n0 + row) * FBINS + kg];
            } else if (kg < 2 * FBINS) {
                a = xim[(size_t)(m0 + row) * FBINS + (kg - FBINS)];
                b = sgn * W1p[(size_t)(n0 + row) * FBINS + (kg - FBINS)];
            }
            ea[it] = a; eb[it] = b;
        }
    };

    auto sts = [&](int buf) {
        #pragma unroll
        for (int it = 0; it < 8; it++) {
            int idx = it * 256 + tid;
            int row = idx >> 4, kl = idx & 15;
            int panel = kl >> 3, kk = kl & 7;
            int col = (kk & 3) * 2 + (kk >> 2);
            sA[buf][panel][row][col] = f2tf32(ea[it]);
            sB[buf][panel][row][col] = f2tf32(eb[it]);
        }
    };

    auto compute = [&](int buf) {
        #pragma unroll
        for (int p = 0; p < 2; p++) {
            uint32_t af[4][4];
            #pragma unroll
            for (int mt = 0; mt < 4; mt++) {
                int r = wm * 64 + mt * 16 + g;
                uint2 lo = *(const uint2*)&sA[buf][p][r][tg * 2];
                uint2 hi = *(const uint2*)&sA[buf][p][r + 8][tg * 2];
                af[mt][0] = lo.x; af[mt][2] = lo.y;
                af[mt][1] = hi.x; af[mt][3] = hi.y;
            }
            #pragma unroll
            for (int nt = 0; nt < 4; nt++) {
                int n = wn * 32 + nt * 8 + g;
                uint2 bb = *(const uint2*)&sB[buf][p][n][tg * 2];
                #pragma unroll
                for (int mt = 0; mt < 4; mt++)
                    mma8(acc[mt][nt], af[mt][0], af[mt][1], af[mt][2], af[mt][3],
                         bb.x, bb.y);
            }
        }
    };

    ldg(0); sts(0);
    __syncthreads();
    #pragma unroll 1
    for (int kb = 0; kb < NKB; kb++) {
        int cur = kb & 1;
        if (kb + 1 < NKB) ldg(kb + 1);
        compute(cur);
        if (kb + 1 < NKB) sts(cur ^ 1);
        __syncthreads();
    }

    const float* biasp = which ? bim : bre;
    float* outp = out + (size_t)which * EMB_M * DM;

    #pragma unroll
    for (int mt = 0; mt < 4; mt++) {
        int r0 = m0 + wm * 64 + mt * 16 + g;
        int r1 = r0 + 8;
        #pragma unroll
        for (int nt = 0; nt < 4; nt++) {
            int cb = n0 + wn * 32 + nt * 8 + tg * 2;
            float* c = acc[mt][nt];
            float2 bi = *(const float2*)&biasp[cb];
            float2 o0 = make_float2(c[0] + bi.x, c[1] + bi.y);
            float2 o1 = make_float2(c[2] + bi.x, c[3] + bi.y);
            *(float2*)&outp[(size_t)r0 * DM + cb] = o0;
            *(float2*)&outp[(size_t)r1 * DM + cb] = o1;
        }
    }
}

// ---------------------------------------------------------------- launch
extern "C" void kernel_launch(void* const* d_in, const int* in_sizes, int n_in,
                              void* d_out, int out_size)
{
    const float* x_re   = (const float*)d_in[0];
    const float* x_im   = (const float*)d_in[1];
    const float* embWre = (const float*)d_in[2];
    const float* embWim = (const float*)d_in[3];
    const float* embbre = (const float*)d_in[4];
    const float* embbim = (const float*)d_in[5];
    const float* W1     = (const float*)d_in[6];
    const float* b1     = (const float*)d_in[7];
    const float* W2     = (const float*)d_in[8];
    const float* b2     = (const float*)d_in[9];
    const float* gamma1 = (const float*)d_in[10];
    const float* beta1  = (const float*)d_in[11];
    const float* gamma2 = (const float*)d_in[12];
    const float* beta2  = (const float*)d_in[13];
    float* out = (float*)d_out;

    float* act = nullptr; float* src = nullptr; float* ff = nullptr;
    float* w1m = nullptr; float* b1m = nullptr; float* w2m = nullptr;
    cudaGetSymbolAddress((void**)&act, g_act);
    cudaGetSymbolAddress((void**)&src, g_src);
    cudaGetSymbolAddress((void**)&ff,  g_ff);
    cudaGetSymbolAddress((void**)&w1m, g_w1m);
    cudaGetSymbolAddress((void**)&b1m, g_b1m);
    cudaGetSymbolAddress((void**)&w2m, g_w2m);

    cudaFuncSetAttribute(k_ffgemm<0>, cudaFuncAttributeMaxDynamicSharedMemorySize, DYNSM);
    cudaFuncSetAttribute(k_ffgemm<1>, cudaFuncAttributeMaxDynamicSharedMemorySize, DYNSM);

    k_init_affine<<<1, DM>>>();

    {
        dim3 grid(2, EMB_M / 128, 2);
        k_embed<<<grid, 256>>>(act, x_re, x_im, embWre, embWim, embbre, embbim);
    }

    float* Pre = ff;
    float* Pim = ff + (size_t)EMB_M * DM;

    const int post_blocks = (int)(((size_t)EMB_M * DM / 4 + 255) / 256);

    for (int l = 0; l < NL; l++) {
        const float* W1l = W1 + (size_t)l * DFF * DM;
        const float* b1l = b1 + (size_t)l * DFF;
        const float* W2l = W2 + (size_t)l * DM * DFF;
        const float* b2l = b2 + (size_t)l * DM;

        {
            dim3 gpre((CC + 31) / 32, DM / 32, BB);
            k_attn_pre<<<gpre, 256>>>(act, Pre, Pim);
            k_attn_post<<<post_blocks, 256>>>(act, Pre, Pim, src);
        }

        k_stats<<<NSTATB, DM>>>(src);
        k_finalize<<<1, DM>>>(gamma1 + l * DM, beta1 + l * DM);
        k_fold<<<DFF, DM>>>(W1l, b1l);
        k_roundW2<<<(DM * DFF) / 256, 256>>>(W2l);

        {
            dim3 g1(DFF / 128, MROWS / 128);
            k_ffgemm<0><<<g1, 128, DYNSM>>>(src, w1m, b1m, nullptr, ff);
            dim3 g2(DM / 128, MROWS / 128);
            k_ffgemm<1><<<g2, 128, DYNSM>>>(ff, w2m, b2l, src, act);
        }

        k_stats<<<NSTATB, DM>>>(act);
        k_finalize<<<1, DM>>>(gamma2 + l * DM, beta2 + l * DM);
    }

    const size_t NO = (size_t)BB * CC * DM;
    k_out<<<(int)((NO + 255) / 256), 256>>>(act, out);
}

// round 8
// speedup vs baseline: 3.8972x; 1.2593x over previous
#include <cuda_runtime.h>
#include <cuda_fp16.h>
#include <math.h>
#include <stdint.h>

// ---------------------------------------------------------------- shapes
#define BB      64
#define CC      862
#define FBINS   257
#define DM      256
#define DFF     512
#define NL      3
#define EPSV    1e-5f

#define EMB_M   (BB*CC)                 // 55168
#define MROWS   (2*BB*CC)               // 110336
#define NSTATB  431
#define ROWS_PER_STATB 256              // 431*256 = 110336

// ---------------------------------------------------------------- scratch
__device__ float  g_act[(size_t)MROWS * DM];
__device__ float  g_src[(size_t)MROWS * DM];
__device__ __half g_srch[(size_t)MROWS * DM];         // fp16 copy of src
__device__ __half g_ffh[(size_t)MROWS * DFF];         // fp16 FF hidden
__device__ float  g_P  [(size_t)MROWS * DM];          // attn transposed scratch
__device__ float  g_psum[NSTATB * DM];
__device__ float  g_psq [NSTATB * DM];
__device__ float  g_al[DM];
__device__ float  g_bt[DM];
__device__ __half g_w1h[DFF * DM];                    // W1 * BN1-affine, fp16
__device__ float  g_b1m[DFF];
__device__ __half g_w2h[NL * DM * DFF];               // W2 fp16 (all layers)

// ---------------------------------------------------------------- helpers
__device__ __forceinline__ uint32_t f2tf32(float x) {
    uint32_t r;
    asm("cvt.rna.tf32.f32 %0, %1;" : "=r"(r) : "f"(x));
    return r;
}

__device__ __forceinline__ uint32_t smem_u32(const void* p) {
    uint32_t a;
    asm("{ .reg .u64 t; cvta.to.shared.u64 t, %1; cvt.u32.u64 %0, t; }" : "=r"(a) : "l"(p));
    return a;
}

__device__ __forceinline__ void cp16(uint32_t dst, const void* src) {
    asm volatile("cp.async.cg.shared.global [%0], [%1], 16;" :: "r"(dst), "l"(src));
}
#define CP_COMMIT() asm volatile("cp.async.commit_group;" ::: "memory")
#define CP_WAIT2()  asm volatile("cp.async.wait_group 2;" ::: "memory")

__device__ __forceinline__ void ldsm4(uint32_t& r0, uint32_t& r1,
                                      uint32_t& r2, uint32_t& r3, uint32_t a) {
    asm volatile("ldmatrix.sync.aligned.m8n8.x4.shared.b16 {%0,%1,%2,%3}, [%4];"
        : "=r"(r0), "=r"(r1), "=r"(r2), "=r"(r3) : "r"(a));
}

// tf32 m16n8k8 (embed path)
__device__ __forceinline__ void mma8(float* c,
    uint32_t a0, uint32_t a1, uint32_t a2, uint32_t a3,
    uint32_t b0, uint32_t b1)
{
    asm volatile(
        "mma.sync.aligned.m16n8k8.row.col.f32.tf32.tf32.f32 "
        "{%0,%1,%2,%3}, {%4,%5,%6,%7}, {%8,%9}, {%0,%1,%2,%3};"
        : "+f"(c[0]), "+f"(c[1]), "+f"(c[2]), "+f"(c[3])
        : "r"(a0), "r"(a1), "r"(a2), "r"(a3), "r"(b0), "r"(b1));
}

// fp16 m16n8k16 (ff path)
__device__ __forceinline__ void mma16(float* c,
    uint32_t a0, uint32_t a1, uint32_t a2, uint32_t a3,
    uint32_t b0, uint32_t b1)
{
    asm volatile(
        "mma.sync.aligned.m16n8k16.row.col.f32.f16.f16.f32 "
        "{%0,%1,%2,%3}, {%4,%5,%6,%7}, {%8,%9}, {%0,%1,%2,%3};"
        : "+f"(c[0]), "+f"(c[1]), "+f"(c[2]), "+f"(c[3])
        : "r"(a0), "r"(a1), "r"(a2), "r"(a3), "r"(b0), "r"(b1));
}

__device__ __forceinline__ float gelu_exact(float h) {
    return 0.5f * h * (1.0f + erff(h * 0.70710678118654752f));
}

// ---------------------------------------------------------------- misc kernels
__global__ void k_init_affine() { g_al[threadIdx.x] = 1.0f; g_bt[threadIdx.x] = 0.0f; }

// ---------------- attention pass 1: compute o_re/o_im, store TRANSPOSED ----
// Pre = g_P[0:half], Pim = g_P[half:]
__global__ __launch_bounds__(256) void k_attn_pre(
    const float* __restrict__ act, float* __restrict__ Pre, float* __restrict__ Pim)
{
    __shared__ float sre[32][33];
    __shared__ float sim[32][33];
    const int c0 = blockIdx.x * 32;
    const int d0 = blockIdx.y * 32;
    const int b  = blockIdx.z;
    const int tx = threadIdx.x & 31;
    const int ty = threadIdx.x >> 5;

    const int d2 = d0 + tx;
    const int d3 = (DM - 1) - d2;
    const float al2 = g_al[d2], bt2 = g_bt[d2];
    const float al3 = g_al[d3], bt3 = g_bt[d3];

    #pragma unroll
    for (int rr = 0; rr < 4; rr++) {
        int c2l = ty + rr * 8;
        int c2 = c0 + c2l;
        if (c2 < CC) {
            int c3 = (CC - 1) - c2;
            float qr = act[((size_t)b        * CC + c2) * DM + d2] * al2 + bt2;
            float qi = act[((size_t)(64 + b) * CC + c2) * DM + d2] * al2 + bt2;
            float kr = act[((size_t)b        * CC + c3) * DM + d3] * al3 + bt3;
            float ki = act[((size_t)(64 + b) * CC + c3) * DM + d3] * al3 + bt3;
            float asr = qr * kr - qi * ki;
            float asi = qr * ki - qi * kr;
            sre[c2l][tx] = 0.25f * (asr - asi) * qr;
            sim[c2l][tx] = 0.25f * (asr + asi) * qr;
        }
    }
    __syncthreads();
    #pragma unroll
    for (int rr = 0; rr < 4; rr++) {
        int d2l = ty + rr * 8;
        int c2 = c0 + tx;
        if (c2 < CC) {
            size_t o = ((size_t)b * DM + (d0 + d2l)) * CC + c2;
            Pre[o] = sre[tx][d2l];
            Pim[o] = sim[tx][d2l];
        }
    }
}

// ---------------- attention pass 2: src = y*affine + P; also fp16 copy -----
__global__ void k_attn_post(
    const float* __restrict__ act, const float* __restrict__ Pre,
    const float* __restrict__ Pim, float* __restrict__ src,
    __half* __restrict__ srch)
{
    size_t idx = (size_t)blockIdx.x * blockDim.x + threadIdx.x;   // float4 index
    if (idx >= (size_t)EMB_M * DM / 4) return;

    float4 al, bt;
    {
        size_t e = idx * 4;
        int d = (int)(e & 255);
        al = *(const float4*)&g_al[d];
        bt = *(const float4*)&g_bt[d];
    }
    const float4* a4 = (const float4*)act;
    float4 a0 = a4[idx];
    float4 a1 = a4[idx + (size_t)EMB_M * DM / 4];
    float4 p0 = ((const float4*)Pre)[idx];
    float4 p1 = ((const float4*)Pim)[idx];

    float4 o0, o1;
    o0.x = a0.x * al.x + bt.x + p0.x;  o0.y = a0.y * al.y + bt.y + p0.y;
    o0.z = a0.z * al.z + bt.z + p0.z;  o0.w = a0.w * al.w + bt.w + p0.w;
    o1.x = a1.x * al.x + bt.x + p1.x;  o1.y = a1.y * al.y + bt.y + p1.y;
    o1.z = a1.z * al.z + bt.z + p1.z;  o1.w = a1.w * al.w + bt.w + p1.w;

    ((float4*)src)[idx] = o0;
    ((float4*)src)[idx + (size_t)EMB_M * DM / 4] = o1;

    __half2 h0 = __floats2half2_rn(o0.x, o0.y);
    __half2 h1 = __floats2half2_rn(o0.z, o0.w);
    __half2 h2 = __floats2half2_rn(o1.x, o1.y);
    __half2 h3 = __floats2half2_rn(o1.z, o1.w);
    ((__half2*)srch)[idx * 2 + 0] = h0;
    ((__half2*)srch)[idx * 2 + 1] = h1;
    ((__half2*)srch)[((size_t)EMB_M * DM / 4 + idx) * 2 + 0] = h2;
    ((__half2*)srch)[((size_t)EMB_M * DM / 4 + idx) * 2 + 1] = h3;
}

__global__ void k_stats(const float* __restrict__ buf)
{
    int ch = threadIdx.x;
    int blk = blockIdx.x;
    float s = 0.0f, q = 0.0f;
    size_t row0 = (size_t)blk * ROWS_PER_STATB;
    #pragma unroll 8
    for (int i = 0; i < ROWS_PER_STATB; i++) {
        float v = buf[(row0 + i) * DM + ch];
        s += v; q += v * v;
    }
    g_psum[blk * DM + ch] = s;
    g_psq [blk * DM + ch] = q;
}

__global__ void k_finalize(const float* __restrict__ gamma, const float* __restrict__ beta)
{
    int ch = threadIdx.x;
    float s = 0.0f, q = 0.0f;
    for (int i = 0; i < NSTATB; i++) { s += g_psum[i * DM + ch]; q += g_psq[i * DM + ch]; }
    const float inv = 1.0f / (float)MROWS;
    float m = s * inv;
    float v = q * inv - m * m;
    float al = gamma[ch] * rsqrtf(v + EPSV);
    g_al[ch] = al;
    g_bt[ch] = beta[ch] - m * al;
}

// fold BN1 affine into W1/b1; store W1' in fp16
__global__ __launch_bounds__(256) void k_fold(const float* __restrict__ W1,
                                              const float* __restrict__ b1)
{
    __shared__ float red[256];
    int f = blockIdx.x;
    int t = threadIdx.x;
    float w = W1[(size_t)f * DM + t];
    g_w1h[(size_t)f * DM + t] = __float2half_rn(w * g_al[t]);
    red[t] = w * g_bt[t];
    __syncthreads();
    #pragma unroll
    for (int s = 128; s > 0; s >>= 1) {
        if (t < s) red[t] += red[t + s];
        __syncthreads();
    }
    if (t == 0) g_b1m[f] = b1[f] + red[0];
}

// fp16-convert all W2 layers once
__global__ void k_roundW2(const float* __restrict__ W2)
{
    int i = blockIdx.x * 256 + threadIdx.x;   // NL*DM*DFF
    g_w2h[i] = __float2half_rn(W2[i]);
}

__global__ void k_out(const float* __restrict__ act, float* __restrict__ out)
{
    size_t e = (size_t)blockIdx.x * blockDim.x + threadIdx.x;
    if (e >= (size_t)BB * CC * DM) return;
    int d = (int)(e & 255);
    size_t r = e >> 8;
    float al = g_al[d], bt = g_bt[d];
    float v0 = act[r * DM + d] * al + bt;
    float v1 = act[((size_t)EMB_M + r) * DM + d] * al + bt;
    *(float2*)&out[2 * e] = make_float2(v0, v1);
}

// ---------------------------------------------------------------- ff GEMMs (fp16 mma + cp.async + ldmatrix)
// MODE 0: ff1 : ffh[M,512] = fp16(gelu( srch[M,256] @ w1h^T + b1m ))
// MODE 1: ff2 : act[M,256] = ffh[M,512] @ w2h^T + b2 + (src*al+bt)
// CTA tile 128x128, 128 threads = 4 warps (2M x 2N), warp tile 64x64.
// BK=32 fp16, 4-stage cp.async pipeline, 80-byte padded rows (conflict-free).
#define RSH     40                        // row stride in halves (80 bytes)
#define STG     4
#define CHUNK_H (128 * RSH)               // halves per tile per stage
#define CHUNK_B (CHUNK_H * 2)             // bytes per tile per stage (10240)
#define DYNSM   (STG * CHUNK_B * 2)       // A + B rings = 81920 bytes

template<int MODE>
__global__ __launch_bounds__(128) void k_ffgemm(
    const __half* __restrict__ A,  const __half* __restrict__ Bm,
    const float* __restrict__ bias, const float* __restrict__ src,
    float* __restrict__ outf, __half* __restrict__ outh)
{
    constexpr int KK   = (MODE == 0) ? DM : DFF;
    constexpr int NKB  = KK / 32;
    constexpr int ASTR = KK;
    constexpr int OSTR = (MODE == 0) ? DFF : DM;

    extern __shared__ __half dynh[];
    __half* pA = dynh;                     // [STG][128][RSH]
    __half* pB = dynh + STG * CHUNK_H;

    const int tid  = threadIdx.x;
    const int lane = tid & 31;
    const int w    = tid >> 5;
    const int wm   = w & 1;      // 0..1  (M)
    const int wn   = w >> 1;     // 0..1  (N)
    const int m0   = blockIdx.y * 128;
    const int n0   = blockIdx.x * 128;
    const int g    = lane >> 2;  // 0..7
    const int tg   = lane & 3;   // 0..3

    const uint32_t baseA = smem_u32(pA);
    const uint32_t baseB = smem_u32(pB);

    // ldmatrix per-lane offsets (bytes) within a chunk tile
    const int lr = lane & 7;
    const int b3 = (lane >> 3) & 1;   // lanes 8-15, 24-31
    const int b4 = (lane >> 4) & 1;   // lanes 16-31
    uint32_t offA[4], offB[4];
    #pragma unroll
    for (int mt = 0; mt < 4; mt++) {
        int row = wm * 64 + mt * 16 + lr + b3 * 8;
        offA[mt] = (uint32_t)(row * (RSH * 2) + b4 * 16);
    }
    #pragma unroll
    for (int ntp = 0; ntp < 4; ntp++) {
        int row = wn * 64 + ntp * 16 + lr + b4 * 8;
        offB[ntp] = (uint32_t)(row * (RSH * 2) + b3 * 16);
    }

    float acc[4][8][4];
    #pragma unroll
    for (int mt = 0; mt < 4; mt++)
        #pragma unroll
        for (int nt = 0; nt < 8; nt++)
            #pragma unroll
            for (int i = 0; i < 4; i++) acc[mt][nt][i] = 0.0f;

    const int srow = tid >> 2, skq = tid & 3;   // 32 rows/step, 4 16B-segments

    auto issue = [&](int kb, int s) {
        uint32_t dA = baseA + (uint32_t)s * CHUNK_B;
        uint32_t dB = baseB + (uint32_t)s * CHUNK_B;
        #pragma unroll
        for (int it = 0; it < 4; it++) {
            int row = it * 32 + srow;
            int kg  = kb * 32 + skq * 8;   // halves
            cp16(dA + row * (RSH * 2) + skq * 16, &A [(size_t)(m0 + row) * ASTR + kg]);
            cp16(dB + row * (RSH * 2) + skq * 16, &Bm[(size_t)(n0 + row) * ASTR + kg]);
        }
    };

    auto compute = [&](int s) {
        uint32_t cA = baseA + (uint32_t)s * CHUNK_B;
        uint32_t cB = baseB + (uint32_t)s * CHUNK_B;
        #pragma unroll
        for (int p = 0; p < 2; p++) {   // two k16 steps per BK=32 chunk
            uint32_t af[4][4];
            #pragma unroll
            for (int mt = 0; mt < 4; mt++)
                ldsm4(af[mt][0], af[mt][1], af[mt][2], af[mt][3],
                      cA + offA[mt] + p * 32);
            uint32_t bf[8][2];
            #pragma unroll
            for (int ntp = 0; ntp < 4; ntp++)
                ldsm4(bf[2 * ntp][0], bf[2 * ntp][1],
                      bf[2 * ntp + 1][0], bf[2 * ntp + 1][1],
                      cB + offB[ntp] + p * 32);
            #pragma unroll
            for (int mt = 0; mt < 4; mt++)
                #pragma unroll
                for (int nt = 0; nt < 8; nt++)
                    mma16(acc[mt][nt], af[mt][0], af[mt][1], af[mt][2], af[mt][3],
                          bf[nt][0], bf[nt][1]);
        }
    };

    issue(0, 0); CP_COMMIT();
    issue(1, 1); CP_COMMIT();
    issue(2, 2); CP_COMMIT();

    #pragma unroll 1
    for (int kb = 0; kb < NKB; kb++) {
        CP_WAIT2();
        __syncthreads();
        if (kb + 3 < NKB) { issue(kb + 3, (kb + 3) & 3); }
        CP_COMMIT();
        compute(kb & 3);
    }

    // ---- epilogue
    #pragma unroll
    for (int mt = 0; mt < 4; mt++) {
        int r0 = m0 + wm * 64 + mt * 16 + g;
        int r1 = r0 + 8;
        #pragma unroll
        for (int nt = 0; nt < 8; nt++) {
            int cb = n0 + wn * 64 + nt * 8 + tg * 2;
            float* c = acc[mt][nt];
            float2 bi = *(const float2*)&bias[cb];
            if (MODE == 0) {
                __half2 h0 = __floats2half2_rn(gelu_exact(c[0] + bi.x),
                                               gelu_exact(c[1] + bi.y));
                __half2 h1 = __floats2half2_rn(gelu_exact(c[2] + bi.x),
                                               gelu_exact(c[3] + bi.y));
                *(__half2*)&outh[(size_t)r0 * OSTR + cb] = h0;
                *(__half2*)&outh[(size_t)r1 * OSTR + cb] = h1;
            } else {
                float2 al = *(const float2*)&g_al[cb];
                float2 bt = *(const float2*)&g_bt[cb];
                float2 s0 = *(const float2*)&src[(size_t)r0 * DM + cb];
                float2 s1 = *(const float2*)&src[(size_t)r1 * DM + cb];
                float2 o0 = make_float2(c[0] + bi.x + s0.x * al.x + bt.x,
                                        c[1] + bi.y + s0.y * al.y + bt.y);
                float2 o1 = make_float2(c[2] + bi.x + s1.x * al.x + bt.x,
                                        c[3] + bi.y + s1.y * al.y + bt.y);
                *(float2*)&outf[(size_t)r0 * OSTR + cb] = o0;
                *(float2*)&outf[(size_t)r1 * OSTR + cb] = o1;
            }
        }
    }
}

// ---------------------------------------------------------------- embedding GEMM (proven R3 path, tf32)
__global__ __launch_bounds__(256) void k_embed(
    float* __restrict__ out,
    const float* __restrict__ xre, const float* __restrict__ xim,
    const float* __restrict__ Wre, const float* __restrict__ Wim,
    const float* __restrict__ bre, const float* __restrict__ bim)
{
    constexpr int NKB = 33;   // 528 / 16

    __shared__ uint32_t sA[2][2][128][8];
    __shared__ uint32_t sB[2][2][128][8];

    const int tid  = threadIdx.x;
    const int lane = tid & 31;
    const int w    = tid >> 5;
    const int wm   = w & 1;
    const int wn   = w >> 1;
    const int m0   = blockIdx.y * 128;
    const int n0   = blockIdx.x * 128;
    const int g    = lane >> 2;
    const int tg   = lane & 3;

    const int which = blockIdx.z;
    const float* W0  = which ? Wim : Wre;
    const float* W1p = which ? Wre : Wim;
    const float  sgn = which ? 1.0f : -1.0f;

    float acc[4][4][4];
    #pragma unroll
    for (int mt = 0; mt < 4; mt++)
        #pragma unroll
        for (int nt = 0; nt < 4; nt++)
            #pragma unroll
            for (int i = 0; i < 4; i++) acc[mt][nt][i] = 0.0f;

    float ea[8], eb[8];

    auto ldg = [&](int kb) {
        #pragma unroll
        for (int it = 0; it < 8; it++) {
            int idx = it * 256 + tid;
            int row = idx >> 4, kl = idx & 15;
            int kg = kb * 16 + kl;
            float a = 0.0f, b = 0.0f;
            if (kg < FBINS) {
                a = xre[(size_t)(m0 + row) * FBINS + kg];
                b = W0 [(size_t)(n0 + row) * FBINS + kg];
            } else if (kg < 2 * FBINS) {
                a = xim[(size_t)(m0 + row) * FBINS + (kg - FBINS)];
                b = sgn * W1p[(size_t)(n0 + row) * FBINS + (kg - FBINS)];
            }
            ea[it] = a; eb[it] = b;
        }
    };

    auto sts = [&](int buf) {
        #pragma unroll
        for (int it = 0; it < 8; it++) {
            int idx = it * 256 + tid;
            int row = idx >> 4, kl = idx & 15;
            int panel = kl >> 3, kk = kl & 7;
            int col = (kk & 3) * 2 + (kk >> 2);
            sA[buf][panel][row][col] = f2tf32(ea[it]);
            sB[buf][panel][row][col] = f2tf32(eb[it]);
        }
    };

    auto compute = [&](int buf) {
        #pragma unroll
        for (int p = 0; p < 2; p++) {
            uint32_t af[4][4];
            #pragma unroll
            for (int mt = 0; mt < 4; mt++) {
                int r = wm * 64 + mt * 16 + g;
                uint2 lo = *(const uint2*)&sA[buf][p][r][tg * 2];
                uint2 hi = *(const uint2*)&sA[buf][p][r + 8][tg * 2];
                af[mt][0] = lo.x; af[mt][2] = lo.y;
                af[mt][1] = hi.x; af[mt][3] = hi.y;
            }
            #pragma unroll
            for (int nt = 0; nt < 4; nt++) {
                int n = wn * 32 + nt * 8 + g;
                uint2 bb = *(const uint2*)&sB[buf][p][n][tg * 2];
                #pragma unroll
                for (int mt = 0; mt < 4; mt++)
                    mma8(acc[mt][nt], af[mt][0], af[mt][1], af[mt][2], af[mt][3],
                         bb.x, bb.y);
            }
        }
    };

    ldg(0); sts(0);
    __syncthreads();
    #pragma unroll 1
    for (int kb = 0; kb < NKB; kb++) {
        int cur = kb & 1;
        if (kb + 1 < NKB) ldg(kb + 1);
        compute(cur);
        if (kb + 1 < NKB) sts(cur ^ 1);
        __syncthreads();
    }

    const float* biasp = which ? bim : bre;
    float* outp = out + (size_t)which * EMB_M * DM;

    #pragma unroll
    for (int mt = 0; mt < 4; mt++) {
        int r0 = m0 + wm * 64 + mt * 16 + g;
        int r1 = r0 + 8;
        #pragma unroll
        for (int nt = 0; nt < 4; nt++) {
            int cb = n0 + wn * 32 + nt * 8 + tg * 2;
            float* c = acc[mt][nt];
            float2 bi = *(const float2*)&biasp[cb];
            float2 o0 = make_float2(c[0] + bi.x, c[1] + bi.y);
            float2 o1 = make_float2(c[2] + bi.x, c[3] + bi.y);
            *(float2*)&outp[(size_t)r0 * DM + cb] = o0;
            *(float2*)&outp[(size_t)r1 * DM + cb] = o1;
        }
    }
}

// ---------------------------------------------------------------- launch
extern "C" void kernel_launch(void* const* d_in, const int* in_sizes, int n_in,
                              void* d_out, int out_size)
{
    const float* x_re   = (const float*)d_in[0];
    const float* x_im   = (const float*)d_in[1];
    const float* embWre = (const float*)d_in[2];
    const float* embWim = (const float*)d_in[3];
    const float* embbre = (const float*)d_in[4];
    const float* embbim = (const float*)d_in[5];
    const float* W1     = (const float*)d_in[6];
    const float* b1     = (const float*)d_in[7];
    const float* W2     = (const float*)d_in[8];
    const float* b2     = (const float*)d_in[9];
    const float* gamma1 = (const float*)d_in[10];
    const float* beta1  = (const float*)d_in[11];
    const float* gamma2 = (const float*)d_in[12];
    const float* beta2  = (const float*)d_in[13];
    float* out = (float*)d_out;

    float*  act  = nullptr; float*  src = nullptr; __half* srch = nullptr;
    __half* ffh  = nullptr; float*  P   = nullptr;
    __half* w1h  = nullptr; float*  b1m = nullptr; __half* w2h  = nullptr;
    cudaGetSymbolAddress((void**)&act,  g_act);
    cudaGetSymbolAddress((void**)&src,  g_src);
    cudaGetSymbolAddress((void**)&srch, g_srch);
    cudaGetSymbolAddress((void**)&ffh,  g_ffh);
    cudaGetSymbolAddress((void**)&P,    g_P);
    cudaGetSymbolAddress((void**)&w1h,  g_w1h);
    cudaGetSymbolAddress((void**)&b1m,  g_b1m);
    cudaGetSymbolAddress((void**)&w2h,  g_w2h);

    cudaFuncSetAttribute(k_ffgemm<0>, cudaFuncAttributeMaxDynamicSharedMemorySize, DYNSM);
    cudaFuncSetAttribute(k_ffgemm<1>, cudaFuncAttributeMaxDynamicSharedMemorySize, DYNSM);

    k_init_affine<<<1, DM>>>();
    k_roundW2<<<(NL * DM * DFF) / 256, 256>>>(W2);

    {
        dim3 grid(2, EMB_M / 128, 2);
        k_embed<<<grid, 256>>>(act, x_re, x_im, embWre, embWim, embbre, embbim);
    }

    float* Pre = P;
    float* Pim = P + (size_t)EMB_M * DM;

    const int post_blocks = (int)(((size_t)EMB_M * DM / 4 + 255) / 256);

    for (int l = 0; l < NL; l++) {
        const float* W1l = W1 + (size_t)l * DFF * DM;
        const float* b1l = b1 + (size_t)l * DFF;
        const float* b2l = b2 + (size_t)l * DM;
        __half* w2hl = w2h + (size_t)l * DM * DFF;

        {
            dim3 gpre((CC + 31) / 32, DM / 32, BB);
            k_attn_pre<<<gpre, 256>>>(act, Pre, Pim);
            k_attn_post<<<post_blocks, 256>>>(act, Pre, Pim, src, srch);
        }

        k_stats<<<NSTATB, DM>>>(src);
        k_finalize<<<1, DM>>>(gamma1 + l * DM, beta1 + l * DM);
        k_fold<<<DFF, DM>>>(W1l, b1l);

        {
            dim3 g1(DFF / 128, MROWS / 128);
            k_ffgemm<0><<<g1, 128, DYNSM>>>(srch, w1h, b1m, nullptr, nullptr, ffh);
            dim3 g2(DM / 128, MROWS / 128);
            k_ffgemm<1><<<g2, 128, DYNSM>>>(ffh, w2hl, b2l, src, act, nullptr);
        }

        k_stats<<<NSTATB, DM>>>(act);
        k_finalize<<<1, DM>>>(gamma2 + l * DM, beta2 + l * DM);
    }

    const size_t NO = (size_t)BB * CC * DM;
    k_out<<<(int)((NO + 255) / 256), 256>>>(act, out);
}

// round 9
// speedup vs baseline: 4.7510x; 1.2191x over previous
#include <cuda_runtime.h>
#include <cuda_fp16.h>
#include <math.h>
#include <stdint.h>

// ---------------------------------------------------------------- shapes
#define BB      64
#define CC      862
#define FBINS   257
#define DM      256
#define DFF     512
#define NL      3
#define EPSV    1e-5f

#define EMB_M   (BB*CC)                 // 55168
#define MROWS   (2*BB*CC)               // 110336
#define NSTATB  431
#define ROWS_PER_STATB 256              // 431*256 = 110336
#define KEMB    544                     // 514 padded to 17*32

// ---------------------------------------------------------------- scratch
__device__ float  g_act[(size_t)MROWS * DM];
__device__ float  g_src[(size_t)MROWS * DM];
__device__ __half g_srch[(size_t)MROWS * DM];         // fp16 copy of src
__device__ __half g_ffh[(size_t)MROWS * DFF];         // fp16 FF hidden
__device__ float  g_P  [(size_t)MROWS * DM];          // attn scratch; embed A-pack
__device__ float  g_psum[NSTATB * DM];
__device__ float  g_psq [NSTATB * DM];
__device__ float  g_al[DM];
__device__ float  g_bt[DM];
__device__ __half g_w1h[DFF * DM];                    // W1 * BN1-affine, fp16
__device__ float  g_b1m[DFF];
__device__ __half g_w2h[NL * DM * DFF];               // W2 fp16 (all layers)
__device__ __half g_wEh[512 * KEMB];                  // embed B pack, fp16
__device__ float  g_bE[512];                          // embed bias pack

// ---------------------------------------------------------------- helpers
__device__ __forceinline__ uint32_t smem_u32(const void* p) {
    uint32_t a;
    asm("{ .reg .u64 t; cvta.to.shared.u64 t, %1; cvt.u32.u64 %0, t; }" : "=r"(a) : "l"(p));
    return a;
}

__device__ __forceinline__ void cp16(uint32_t dst, const void* src) {
    asm volatile("cp.async.cg.shared.global [%0], [%1], 16;" :: "r"(dst), "l"(src));
}
#define CP_COMMIT() asm volatile("cp.async.commit_group;" ::: "memory")
#define CP_WAIT1()  asm volatile("cp.async.wait_group 1;" ::: "memory")

__device__ __forceinline__ void ldsm4(uint32_t& r0, uint32_t& r1,
                                      uint32_t& r2, uint32_t& r3, uint32_t a) {
    asm volatile("ldmatrix.sync.aligned.m8n8.x4.shared.b16 {%0,%1,%2,%3}, [%4];"
        : "=r"(r0), "=r"(r1), "=r"(r2), "=r"(r3) : "r"(a));
}

// fp16 m16n8k16
__device__ __forceinline__ void mma16(float* c,
    uint32_t a0, uint32_t a1, uint32_t a2, uint32_t a3,
    uint32_t b0, uint32_t b1)
{
    asm volatile(
        "mma.sync.aligned.m16n8k16.row.col.f32.f16.f16.f32 "
        "{%0,%1,%2,%3}, {%4,%5,%6,%7}, {%8,%9}, {%0,%1,%2,%3};"
        : "+f"(c[0]), "+f"(c[1]), "+f"(c[2]), "+f"(c[3])
        : "r"(a0), "r"(a1), "r"(a2), "r"(a3), "r"(b0), "r"(b1));
}

__device__ __forceinline__ float gelu_exact(float h) {
    return 0.5f * h * (1.0f + erff(h * 0.70710678118654752f));
}

// ---------------------------------------------------------------- misc kernels
__global__ void k_init_affine() { g_al[threadIdx.x] = 1.0f; g_bt[threadIdx.x] = 0.0f; }

// ---------------- embed packing ----------------
__global__ void k_packA(const float* __restrict__ xre, const float* __restrict__ xim,
                        __half* __restrict__ Ah)
{
    size_t i = (size_t)blockIdx.x * 256 + threadIdx.x;
    if (i >= (size_t)EMB_M * KEMB) return;
    int k = (int)(i % KEMB);
    size_t m = i / KEMB;
    float v = 0.0f;
    if (k < FBINS)          v = xre[m * FBINS + k];
    else if (k < 2 * FBINS) v = xim[m * FBINS + (k - FBINS)];
    Ah[i] = __float2half_rn(v);
}

__global__ void k_packW(const float* __restrict__ Wre, const float* __restrict__ Wim)
{
    size_t i = (size_t)blockIdx.x * 256 + threadIdx.x;
    if (i >= (size_t)512 * KEMB) return;
    int k = (int)(i % KEMB);
    int n = (int)(i / KEMB);
    float v = 0.0f;
    if (n < 256) {         // which = 0: [Wre | -Wim]
        if (k < FBINS)          v = Wre[n * FBINS + k];
        else if (k < 2 * FBINS) v = -Wim[n * FBINS + (k - FBINS)];
    } else {               // which = 1: [Wim | Wre]
        int nn = n - 256;
        if (k < FBINS)          v = Wim[nn * FBINS + k];
        else if (k < 2 * FBINS) v = Wre[nn * FBINS + (k - FBINS)];
    }
    g_wEh[i] = __float2half_rn(v);
}

__global__ void k_packBias(const float* __restrict__ bre, const float* __restrict__ bim)
{
    int t = threadIdx.x;    // 512
    g_bE[t] = (t < 256) ? bre[t] : bim[t - 256];
}

// ---------------- attention pass 1: compute o_re/o_im, store TRANSPOSED ----
__global__ __launch_bounds__(256) void k_attn_pre(
    const float* __restrict__ act, float* __restrict__ Pre, float* __restrict__ Pim)
{
    __shared__ float sre[32][33];
    __shared__ float sim[32][33];
    const int c0 = blockIdx.x * 32;
    const int d0 = blockIdx.y * 32;
    const int b  = blockIdx.z;
    const int tx = threadIdx.x & 31;
    const int ty = threadIdx.x >> 5;

    const int d2 = d0 + tx;
    const int d3 = (DM - 1) - d2;
    const float al2 = g_al[d2], bt2 = g_bt[d2];
    const float al3 = g_al[d3], bt3 = g_bt[d3];

    #pragma unroll
    for (int rr = 0; rr < 4; rr++) {
        int c2l = ty + rr * 8;
        int c2 = c0 + c2l;
        if (c2 < CC) {
            int c3 = (CC - 1) - c2;
            float qr = act[((size_t)b        * CC + c2) * DM + d2] * al2 + bt2;
            float qi = act[((size_t)(64 + b) * CC + c2) * DM + d2] * al2 + bt2;
            float kr = act[((size_t)b        * CC + c3) * DM + d3] * al3 + bt3;
            float ki = act[((size_t)(64 + b) * CC + c3) * DM + d3] * al3 + bt3;
            float asr = qr * kr - qi * ki;
            float asi = qr * ki - qi * kr;
            sre[c2l][tx] = 0.25f * (asr - asi) * qr;
            sim[c2l][tx] = 0.25f * (asr + asi) * qr;
        }
    }
    __syncthreads();
    #pragma unroll
    for (int rr = 0; rr < 4; rr++) {
        int d2l = ty + rr * 8;
        int c2 = c0 + tx;
        if (c2 < CC) {
            size_t o = ((size_t)b * DM + (d0 + d2l)) * CC + c2;
            Pre[o] = sre[tx][d2l];
            Pim[o] = sim[tx][d2l];
        }
    }
}

// ---------------- attention pass 2: src = y*affine + P; also fp16 copy -----
__global__ void k_attn_post(
    const float* __restrict__ act, const float* __restrict__ Pre,
    const float* __restrict__ Pim, float* __restrict__ src,
    __half* __restrict__ srch)
{
    size_t idx = (size_t)blockIdx.x * blockDim.x + threadIdx.x;   // float4 index
    if (idx >= (size_t)EMB_M * DM / 4) return;

    float4 al, bt;
    {
        size_t e = idx * 4;
        int d = (int)(e & 255);
        al = *(const float4*)&g_al[d];
        bt = *(const float4*)&g_bt[d];
    }
    const float4* a4 = (const float4*)act;
    float4 a0 = a4[idx];
    float4 a1 = a4[idx + (size_t)EMB_M * DM / 4];
    float4 p0 = ((const float4*)Pre)[idx];
    float4 p1 = ((const float4*)Pim)[idx];

    float4 o0, o1;
    o0.x = a0.x * al.x + bt.x + p0.x;  o0.y = a0.y * al.y + bt.y + p0.y;
    o0.z = a0.z * al.z + bt.z + p0.z;  o0.w = a0.w * al.w + bt.w + p0.w;
    o1.x = a1.x * al.x + bt.x + p1.x;  o1.y = a1.y * al.y + bt.y + p1.y;
    o1.z = a1.z * al.z + bt.z + p1.z;  o1.w = a1.w * al.w + bt.w + p1.w;

    ((float4*)src)[idx] = o0;
    ((float4*)src)[idx + (size_t)EMB_M * DM / 4] = o1;

    __half2 h0 = __floats2half2_rn(o0.x, o0.y);
    __half2 h1 = __floats2half2_rn(o0.z, o0.w);
    __half2 h2 = __floats2half2_rn(o1.x, o1.y);
    __half2 h3 = __floats2half2_rn(o1.z, o1.w);
    ((__half2*)srch)[idx * 2 + 0] = h0;
    ((__half2*)srch)[idx * 2 + 1] = h1;
    ((__half2*)srch)[((size_t)EMB_M * DM / 4 + idx) * 2 + 0] = h2;
    ((__half2*)srch)[((size_t)EMB_M * DM / 4 + idx) * 2 + 1] = h3;
}

__global__ void k_stats(const float* __restrict__ buf)
{
    int ch = threadIdx.x;
    int blk = blockIdx.x;
    float s = 0.0f, q = 0.0f;
    size_t row0 = (size_t)blk * ROWS_PER_STATB;
    #pragma unroll 8
    for (int i = 0; i < ROWS_PER_STATB; i++) {
        float v = buf[(row0 + i) * DM + ch];
        s += v; q += v * v;
    }
    g_psum[blk * DM + ch] = s;
    g_psq [blk * DM + ch] = q;
}

__global__ void k_finalize(const float* __restrict__ gamma, const float* __restrict__ beta)
{
    int ch = threadIdx.x;
    float s = 0.0f, q = 0.0f;
    for (int i = 0; i < NSTATB; i++) { s += g_psum[i * DM + ch]; q += g_psq[i * DM + ch]; }
    const float inv = 1.0f / (float)MROWS;
    float m = s * inv;
    float v = q * inv - m * m;
    float al = gamma[ch] * rsqrtf(v + EPSV);
    g_al[ch] = al;
    g_bt[ch] = beta[ch] - m * al;
}

// fold BN1 affine into W1/b1; store W1' in fp16
__global__ __launch_bounds__(256) void k_fold(const float* __restrict__ W1,
                                              const float* __restrict__ b1)
{
    __shared__ float red[256];
    int f = blockIdx.x;
    int t = threadIdx.x;
    float w = W1[(size_t)f * DM + t];
    g_w1h[(size_t)f * DM + t] = __float2half_rn(w * g_al[t]);
    red[t] = w * g_bt[t];
    __syncthreads();
    #pragma unroll
    for (int s = 128; s > 0; s >>= 1) {
        if (t < s) red[t] += red[t + s];
        __syncthreads();
    }
    if (t == 0) g_b1m[f] = b1[f] + red[0];
}

// fp16-convert all W2 layers once
__global__ void k_roundW2(const float* __restrict__ W2)
{
    int i = blockIdx.x * 256 + threadIdx.x;   // NL*DM*DFF
    g_w2h[i] = __float2half_rn(W2[i]);
}

__global__ void k_out(const float* __restrict__ act, float* __restrict__ out)
{
    size_t e = (size_t)blockIdx.x * blockDim.x + threadIdx.x;
    if (e >= (size_t)BB * CC * DM) return;
    int d = (int)(e & 255);
    size_t r = e >> 8;
    float al = g_al[d], bt = g_bt[d];
    float v0 = act[r * DM + d] * al + bt;
    float v1 = act[((size_t)EMB_M + r) * DM + d] * al + bt;
    *(float2*)&out[2 * e] = make_float2(v0, v1);
}

// ---------------------------------------------------------------- unified fp16 GEMM
// MODE 0: ff1  : ffh[M,512] = fp16(gelu( srch[M,256] @ w1h^T + b1m ))
// MODE 1: ff2  : act[M,256] = ffh[M,512] @ w2h^T + b2 + (src*al+bt)
// MODE 2: embed: act[which][M,256] = Ah[M,544] @ wEh^T + bE  (which = n0>>8)
// CTA tile 128x128, 128 threads = 4 warps (2M x 2N), warp tile 64x64.
// BK=32 fp16, 3-stage cp.async pipeline, 80-byte padded rows.
#define RSH     40                        // row stride in halves (80 bytes)
#define STG     3
#define CHUNK_H (128 * RSH)               // halves per tile per stage
#define CHUNK_B (CHUNK_H * 2)             // bytes per tile per stage (10240)
#define DYNSM   (STG * CHUNK_B * 2)       // A + B rings = 61440 bytes

template<int MODE>
__global__ __launch_bounds__(128, 3) void k_ffgemm(
    const __half* __restrict__ A,  const __half* __restrict__ Bm,
    const float* __restrict__ bias, const float* __restrict__ src,
    float* __restrict__ outf, __half* __restrict__ outh)
{
    constexpr int KK   = (MODE == 0) ? DM : (MODE == 1) ? DFF : KEMB;
    constexpr int NKB  = KK / 32;
    constexpr int ASTR = KK;
    constexpr int OSTR = (MODE == 0) ? DFF : DM;

    extern __shared__ __half dynh[];
    __half* pA = dynh;                     // [STG][128][RSH]
    __half* pB = dynh + STG * CHUNK_H;

    const int tid  = threadIdx.x;
    const int lane = tid & 31;
    const int w    = tid >> 5;
    const int wm   = w & 1;      // 0..1  (M)
    const int wn   = w >> 1;     // 0..1  (N)
    const int m0   = blockIdx.y * 128;
    const int n0   = blockIdx.x * 128;
    const int g    = lane >> 2;  // 0..7
    const int tg   = lane & 3;   // 0..3

    const uint32_t baseA = smem_u32(pA);
    const uint32_t baseB = smem_u32(pB);

    // ldmatrix per-lane offsets (bytes) within a chunk tile
    const int lr = lane & 7;
    const int b3 = (lane >> 3) & 1;
    const int b4 = (lane >> 4) & 1;
    uint32_t offA[4], offB[4];
    #pragma unroll
    for (int mt = 0; mt < 4; mt++) {
        int row = wm * 64 + mt * 16 + lr + b3 * 8;
        offA[mt] = (uint32_t)(row * (RSH * 2) + b4 * 16);
    }
    #pragma unroll
    for (int ntp = 0; ntp < 4; ntp++) {
        int row = wn * 64 + ntp * 16 + lr + b4 * 8;
        offB[ntp] = (uint32_t)(row * (RSH * 2) + b3 * 16);
    }

    float acc[4][8][4];
    #pragma unroll
    for (int mt = 0; mt < 4; mt++)
        #pragma unroll
        for (int nt = 0; nt < 8; nt++)
            #pragma unroll
            for (int i = 0; i < 4; i++) acc[mt][nt][i] = 0.0f;

    const int srow = tid >> 2, skq = tid & 3;

    auto issue = [&](int kb, int s) {
        uint32_t dA = baseA + (uint32_t)s * CHUNK_B;
        uint32_t dB = baseB + (uint32_t)s * CHUNK_B;
        #pragma unroll
        for (int it = 0; it < 4; it++) {
            int row = it * 32 + srow;
            int kg  = kb * 32 + skq * 8;   // halves
            cp16(dA + row * (RSH * 2) + skq * 16, &A [(size_t)(m0 + row) * ASTR + kg]);
            cp16(dB + row * (RSH * 2) + skq * 16, &Bm[(size_t)(n0 + row) * ASTR + kg]);
        }
    };

    auto compute = [&](int s) {
        uint32_t cA = baseA + (uint32_t)s * CHUNK_B;
        uint32_t cB = baseB + (uint32_t)s * CHUNK_B;
        #pragma unroll
        for (int p = 0; p < 2; p++) {
            uint32_t af[4][4];
            #pragma unroll
            for (int mt = 0; mt < 4; mt++)
                ldsm4(af[mt][0], af[mt][1], af[mt][2], af[mt][3],
                      cA + offA[mt] + p * 32);
            uint32_t bf[8][2];
            #pragma unroll
            for (int ntp = 0; ntp < 4; ntp++)
                ldsm4(bf[2 * ntp][0], bf[2 * ntp][1],
                      bf[2 * ntp + 1][0], bf[2 * ntp + 1][1],
                      cB + offB[ntp] + p * 32);
            #pragma unroll
            for (int mt = 0; mt < 4; mt++)
                #pragma unroll
                for (int nt = 0; nt < 8; nt++)
                    mma16(acc[mt][nt], af[mt][0], af[mt][1], af[mt][2], af[mt][3],
                          bf[nt][0], bf[nt][1]);
        }
    };

    issue(0, 0); CP_COMMIT();
    issue(1, 1); CP_COMMIT();

    #pragma unroll 1
    for (int kb = 0; kb < NKB; kb++) {
        CP_WAIT1();                 // group kb complete (only kb+1 may be pending)
        __syncthreads();            // data visible; stage (kb+2)%3 free to refill
        if (kb + 2 < NKB) issue(kb + 2, (kb + 2) % 3);
        CP_COMMIT();
        compute(kb % 3);
    }

    // ---- epilogue
    const int whichv = (MODE == 2) ? (n0 >> 8) : 0;
    float* outfp = (MODE == 2) ? (outf + (size_t)whichv * EMB_M * DM) : outf;
    const int ncorr = (MODE == 2) ? whichv * 256 : 0;

    #pragma unroll
    for (int mt = 0; mt < 4; mt++) {
        int r0 = m0 + wm * 64 + mt * 16 + g;
        int r1 = r0 + 8;
        #pragma unroll
        for (int nt = 0; nt < 8; nt++) {
            int cb = n0 + wn * 64 + nt * 8 + tg * 2;
            float* c = acc[mt][nt];
            float2 bi = *(const float2*)&bias[cb];
            if (MODE == 0) {
                __half2 h0 = __floats2half2_rn(gelu_exact(c[0] + bi.x),
                                               gelu_exact(c[1] + bi.y));
                __half2 h1 = __floats2half2_rn(gelu_exact(c[2] + bi.x),
                                               gelu_exact(c[3] + bi.y));
                *(__half2*)&outh[(size_t)r0 * OSTR + cb] = h0;
                *(__half2*)&outh[(size_t)r1 * OSTR + cb] = h1;
            } else if (MODE == 1) {
                float2 al = *(const float2*)&g_al[cb];
                float2 bt = *(const float2*)&g_bt[cb];
                float2 s0 = *(const float2*)&src[(size_t)r0 * DM + cb];
                float2 s1 = *(const float2*)&src[(size_t)r1 * DM + cb];
                float2 o0 = make_float2(c[0] + bi.x + s0.x * al.x + bt.x,
                                        c[1] + bi.y + s0.y * al.y + bt.y);
                float2 o1 = make_float2(c[2] + bi.x + s1.x * al.x + bt.x,
                                        c[3] + bi.y + s1.y * al.y + bt.y);
                *(float2*)&outf[(size_t)r0 * OSTR + cb] = o0;
                *(float2*)&outf[(size_t)r1 * OSTR + cb] = o1;
            } else {
                int cl = cb - ncorr;
                float2 o0 = make_float2(c[0] + bi.x, c[1] + bi.y);
                float2 o1 = make_float2(c[2] + bi.x, c[3] + bi.y);
                *(float2*)&outfp[(size_t)r0 * OSTR + cl] = o0;
                *(float2*)&outfp[(size_t)r1 * OSTR + cl] = o1;
            }
        }
    }
}

// ---------------------------------------------------------------- launch
extern "C" void kernel_launch(void* const* d_in, const int* in_sizes, int n_in,
                              void* d_out, int out_size)
{
    const float* x_re   = (const float*)d_in[0];
    const float* x_im   = (const float*)d_in[1];
    const float* embWre = (const float*)d_in[2];
    const float* embWim = (const float*)d_in[3];
    const float* embbre = (const float*)d_in[4];
    const float* embbim = (const float*)d_in[5];
    const float* W1     = (const float*)d_in[6];
    const float* b1     = (const float*)d_in[7];
    const float* W2     = (const float*)d_in[8];
    const float* b2     = (const float*)d_in[9];
    const float* gamma1 = (const float*)d_in[10];
    const float* beta1  = (const float*)d_in[11];
    const float* gamma2 = (const float*)d_in[12];
    const float* beta2  = (const float*)d_in[13];
    float* out = (float*)d_out;

    float*  act  = nullptr; float*  src = nullptr; __half* srch = nullptr;
    __half* ffh  = nullptr; float*  P   = nullptr;
    __half* w1h  = nullptr; float*  b1m = nullptr; __half* w2h  = nullptr;
    __half* wEh  = nullptr; float*  bE  = nullptr;
    cudaGetSymbolAddress((void**)&act,  g_act);
    cudaGetSymbolAddress((void**)&src,  g_src);
    cudaGetSymbolAddress((void**)&srch, g_srch);
    cudaGetSymbolAddress((void**)&ffh,  g_ffh);
    cudaGetSymbolAddress((void**)&P,    g_P);
    cudaGetSymbolAddress((void**)&w1h,  g_w1h);
    cudaGetSymbolAddress((void**)&b1m,  g_b1m);
    cudaGetSymbolAddress((void**)&w2h,  g_w2h);
    cudaGetSymbolAddress((void**)&wEh,  g_wEh);
    cudaGetSymbolAddress((void**)&bE,   g_bE);

    cudaFuncSetAttribute(k_ffgemm<0>, cudaFuncAttributeMaxDynamicSharedMemorySize, DYNSM);
    cudaFuncSetAttribute(k_ffgemm<1>, cudaFuncAttributeMaxDynamicSharedMemorySize, DYNSM);
    cudaFuncSetAttribute(k_ffgemm<2>, cudaFuncAttributeMaxDynamicSharedMemorySize, DYNSM);

    k_init_affine<<<1, DM>>>();
    k_roundW2<<<(NL * DM * DFF) / 256, 256>>>(W2);

    // embed: pack fp16 operands, then fp16 GEMM
    __half* Ah = (__half*)P;   // reuse g_P (embed runs before any attn)
    {
        size_t na = (size_t)EMB_M * KEMB;
        k_packA<<<(int)((na + 255) / 256), 256>>>(x_re, x_im, Ah);
        size_t nb = (size_t)512 * KEMB;
        k_packW<<<(int)((nb + 255) / 256), 256>>>(embWre, embWim);
        k_packBias<<<1, 512>>>(embbre, embbim);
        dim3 ge(512 / 128, EMB_M / 128);
        k_ffgemm<2><<<ge, 128, DYNSM>>>(Ah, wEh, bE, nullptr, act, nullptr);
    }

    float* Pre = P;
    float* Pim = P + (size_t)EMB_M * DM;

    const int post_blocks = (int)(((size_t)EMB_M * DM / 4 + 255) / 256);

    for (int l = 0; l < NL; l++) {
        const float* W1l = W1 + (size_t)l * DFF * DM;
        const float* b1l = b1 + (size_t)l * DFF;
        const float* b2l = b2 + (size_t)l * DM;
        __half* w2hl = w2h + (size_t)l * DM * DFF;

        {
            dim3 gpre((CC + 31) / 32, DM / 32, BB);
            k_attn_pre<<<gpre, 256>>>(act, Pre, Pim);
            k_attn_post<<<post_blocks, 256>>>(act, Pre, Pim, src, srch);
        }

        k_stats<<<NSTATB, DM>>>(src);
        k_finalize<<<1, DM>>>(gamma1 + l * DM, beta1 + l * DM);
        k_fold<<<DFF, DM>>>(W1l, b1l);

        {
            dim3 g1(DFF / 128, MROWS / 128);
            k_ffgemm<0><<<g1, 128, DYNSM>>>(srch, w1h, b1m, nullptr, nullptr, ffh);
            dim3 g2(DM / 128, MROWS / 128);
            k_ffgemm<1><<<g2, 128, DYNSM>>>(ffh, w2hl, b2l, src, act, nullptr);
        }

        k_stats<<<NSTATB, DM>>>(act);
        k_finalize<<<1, DM>>>(gamma2 + l * DM, beta2 + l * DM);
    }

    const size_t NO = (size_t)BB * CC * DM;
    k_out<<<(int)((NO + 255) / 256), 256>>>(act, out);
}

// round 10
// speedup vs baseline: 4.9831x; 1.0489x over previous
#include <cuda_runtime.h>
#include <cuda_fp16.h>
#include <math.h>
#include <stdint.h>

// ---------------------------------------------------------------- shapes
#define BB      64
#define CC      862
#define FBINS   257
#define DM      256
#define DFF     512
#define NL      3
#define EPSV    1e-5f

#define EMB_M   (BB*CC)                 // 55168
#define MROWS   (2*BB*CC)               // 110336
#define NSTATB  862
#define ROWS_PER_STATB 128              // 862*128 = 110336
#define KEMB    544                     // 514 padded to 17*32

// ---------------------------------------------------------------- scratch
__device__ float  g_act[(size_t)MROWS * DM];
__device__ float  g_src[(size_t)MROWS * DM];
__device__ __half g_srch[(size_t)MROWS * DM];         // fp16 copy of src
__device__ __half g_ffh[(size_t)MROWS * DFF];         // fp16 FF hidden
__device__ float  g_P  [(size_t)MROWS * DM];          // embed A-pack scratch
__device__ float  g_psum[NSTATB * DM];
__device__ float  g_psq [NSTATB * DM];
__device__ float  g_al[DM];
__device__ float  g_bt[DM];
__device__ __half g_w1h[DFF * DM];                    // W1 * BN1-affine, fp16
__device__ float  g_b1m[DFF];
__device__ __half g_w2h[NL * DM * DFF];               // W2 fp16 (all layers)
__device__ __half g_wEh[512 * KEMB];                  // embed B pack, fp16
__device__ float  g_bE[512];                          // embed bias pack

// ---------------------------------------------------------------- helpers
__device__ __forceinline__ uint32_t smem_u32(const void* p) {
    uint32_t a;
    asm("{ .reg .u64 t; cvta.to.shared.u64 t, %1; cvt.u32.u64 %0, t; }" : "=r"(a) : "l"(p));
    return a;
}

__device__ __forceinline__ void cp16(uint32_t dst, const void* src) {
    asm volatile("cp.async.cg.shared.global [%0], [%1], 16;" :: "r"(dst), "l"(src));
}
#define CP_COMMIT() asm volatile("cp.async.commit_group;" ::: "memory")
#define CP_WAIT1()  asm volatile("cp.async.wait_group 1;" ::: "memory")

__device__ __forceinline__ void ldsm4(uint32_t& r0, uint32_t& r1,
                                      uint32_t& r2, uint32_t& r3, uint32_t a) {
    asm volatile("ldmatrix.sync.aligned.m8n8.x4.shared.b16 {%0,%1,%2,%3}, [%4];"
        : "=r"(r0), "=r"(r1), "=r"(r2), "=r"(r3) : "r"(a));
}

// fp16 m16n8k16
__device__ __forceinline__ void mma16(float* c,
    uint32_t a0, uint32_t a1, uint32_t a2, uint32_t a3,
    uint32_t b0, uint32_t b1)
{
    asm volatile(
        "mma.sync.aligned.m16n8k16.row.col.f32.f16.f16.f32 "
        "{%0,%1,%2,%3}, {%4,%5,%6,%7}, {%8,%9}, {%0,%1,%2,%3};"
        : "+f"(c[0]), "+f"(c[1]), "+f"(c[2]), "+f"(c[3])
        : "r"(a0), "r"(a1), "r"(a2), "r"(a3), "r"(b0), "r"(b1));
}

__device__ __forceinline__ float gelu_exact(float h) {
    return 0.5f * h * (1.0f + erff(h * 0.70710678118654752f));
}

// ---------------------------------------------------------------- misc kernels
__global__ void k_init_affine() { g_al[threadIdx.x] = 1.0f; g_bt[threadIdx.x] = 0.0f; }

// ---------------- embed packing ----------------
__global__ void k_packA(const float* __restrict__ xre, const float* __restrict__ xim,
                        __half* __restrict__ Ah)
{
    size_t i = (size_t)blockIdx.x * 256 + threadIdx.x;
    if (i >= (size_t)EMB_M * KEMB) return;
    int k = (int)(i % KEMB);
    size_t m = i / KEMB;
    float v = 0.0f;
    if (k < FBINS)          v = xre[m * FBINS + k];
    else if (k < 2 * FBINS) v = xim[m * FBINS + (k - FBINS)];
    Ah[i] = __float2half_rn(v);
}

__global__ void k_packW(const float* __restrict__ Wre, const float* __restrict__ Wim)
{
    size_t i = (size_t)blockIdx.x * 256 + threadIdx.x;
    if (i >= (size_t)512 * KEMB) return;
    int k = (int)(i % KEMB);
    int n = (int)(i / KEMB);
    float v = 0.0f;
    if (n < 256) {         // which = 0: [Wre | -Wim]
        if (k < FBINS)          v = Wre[n * FBINS + k];
        else if (k < 2 * FBINS) v = -Wim[n * FBINS + (k - FBINS)];
    } else {               // which = 1: [Wim | Wre]
        int nn = n - 256;
        if (k < FBINS)          v = Wim[nn * FBINS + k];
        else if (k < 2 * FBINS) v = Wre[nn * FBINS + (k - FBINS)];
    }
    g_wEh[i] = __float2half_rn(v);
}

__global__ void k_packBias(const float* __restrict__ bre, const float* __restrict__ bim)
{
    int t = threadIdx.x;    // 512
    g_bE[t] = (t < 256) ? bre[t] : bim[t - 256];
}

// ---------------- FUSED attention: gather -> transpose tile -> residual ----
// Block handles (c2-tile 32, d2-tile 32, b). Phase 1 computes o_re/o_im into
// smem (reads coalesced along d2). Phase 2 exploits e = b*220672 + t with
// t = d2*862 + c2: for fixed d2, destinations are 32-contiguous -> writes
// src/srch directly with the affine residual. No intermediate P buffer.
__global__ __launch_bounds__(256) void k_attn(
    const float* __restrict__ act, float* __restrict__ src,
    __half* __restrict__ srch)
{
    __shared__ float sre[32][33];
    __shared__ float sim[32][33];
    const int c0 = blockIdx.x * 32;
    const int d0 = blockIdx.y * 32;
    const int b  = blockIdx.z;
    const int tx = threadIdx.x & 31;
    const int ty = threadIdx.x >> 5;

    {
        const int d2 = d0 + tx;
        const int d3 = (DM - 1) - d2;
        const float al2 = g_al[d2], bt2 = g_bt[d2];
        const float al3 = g_al[d3], bt3 = g_bt[d3];

        #pragma unroll
        for (int rr = 0; rr < 4; rr++) {
            int c2l = ty + rr * 8;
            int c2 = c0 + c2l;
            if (c2 < CC) {
                int c3 = (CC - 1) - c2;
                float qr = act[((size_t)b        * CC + c2) * DM + d2] * al2 + bt2;
                float qi = act[((size_t)(64 + b) * CC + c2) * DM + d2] * al2 + bt2;
                float kr = act[((size_t)b        * CC + c3) * DM + d3] * al3 + bt3;
                float ki = act[((size_t)(64 + b) * CC + c3) * DM + d3] * al3 + bt3;
                float asr = qr * kr - qi * ki;
                float asi = qr * ki - qi * kr;
                sre[c2l][tx] = 0.25f * (asr - asi) * qr;
                sim[c2l][tx] = 0.25f * (asr + asi) * qr;
            }
        }
    }
    __syncthreads();

    const int c2 = c0 + tx;
    if (c2 < CC) {
        #pragma unroll
        for (int rr = 0; rr < 4; rr++) {
            int d2l = ty + rr * 8;
            int t = (d0 + d2l) * CC + c2;
            int d = t & 255;
            float al = g_al[d], bt = g_bt[d];
            size_t e0 = (size_t)b * (CC * DM) + t;
            size_t e1 = e0 + (size_t)EMB_M * DM;
            float y0 = act[e0] * al + bt + sre[tx][d2l];
            float y1 = act[e1] * al + bt + sim[tx][d2l];
            src[e0] = y0;
            src[e1] = y1;
            srch[e0] = __float2half_rn(y0);
            srch[e1] = __float2half_rn(y1);
        }
    }
}

__global__ void k_stats(const float* __restrict__ buf)
{
    int ch = threadIdx.x;
    int blk = blockIdx.x;
    float s = 0.0f, q = 0.0f;
    size_t row0 = (size_t)blk * ROWS_PER_STATB;
    #pragma unroll 16
    for (int i = 0; i < ROWS_PER_STATB; i++) {
        float v = buf[(row0 + i) * DM + ch];
        s += v; q += v * v;
    }
    g_psum[blk * DM + ch] = s;
    g_psq [blk * DM + ch] = q;
}

__global__ void k_finalize(const float* __restrict__ gamma, const float* __restrict__ beta)
{
    int ch = threadIdx.x;
    float s = 0.0f, q = 0.0f;
    for (int i = 0; i < NSTATB; i++) { s += g_psum[i * DM + ch]; q += g_psq[i * DM + ch]; }
    const float inv = 1.0f / (float)MROWS;
    float m = s * inv;
    float v = q * inv - m * m;
    float al = gamma[ch] * rsqrtf(v + EPSV);
    g_al[ch] = al;
    g_bt[ch] = beta[ch] - m * al;
}

// fold BN1 affine into W1/b1; store W1' in fp16
__global__ __launch_bounds__(256) void k_fold(const float* __restrict__ W1,
                                              const float* __restrict__ b1)
{
    __shared__ float red[256];
    int f = blockIdx.x;
    int t = threadIdx.x;
    float w = W1[(size_t)f * DM + t];
    g_w1h[(size_t)f * DM + t] = __float2half_rn(w * g_al[t]);
    red[t] = w * g_bt[t];
    __syncthreads();
    #pragma unroll
    for (int s = 128; s > 0; s >>= 1) {
        if (t < s) red[t] += red[t + s];
        __syncthreads();
    }
    if (t == 0) g_b1m[f] = b1[f] + red[0];
}

// fp16-convert all W2 layers once
__global__ void k_roundW2(const float* __restrict__ W2)
{
    int i = blockIdx.x * 256 + threadIdx.x;   // NL*DM*DFF
    g_w2h[i] = __float2half_rn(W2[i]);
}

__global__ void k_out(const float* __restrict__ act, float* __restrict__ out)
{
    size_t e = (size_t)blockIdx.x * blockDim.x + threadIdx.x;
    if (e >= (size_t)BB * CC * DM) return;
    int d = (int)(e & 255);
    size_t r = e >> 8;
    float al = g_al[d], bt = g_bt[d];
    float v0 = act[r * DM + d] * al + bt;
    float v1 = act[((size_t)EMB_M + r) * DM + d] * al + bt;
    *(float2*)&out[2 * e] = make_float2(v0, v1);
}

// ---------------------------------------------------------------- unified fp16 GEMM
// MODE 0: ff1  : ffh[M,512] = fp16(gelu( srch[M,256] @ w1h^T + b1m ))
// MODE 1: ff2  : act[M,256] = ffh[M,512] @ w2h^T + b2 + (src*al+bt)
// MODE 2: embed: act[which][M,256] = Ah[M,544] @ wEh^T + bE  (which = n0>>8)
// CTA tile 128x128, 128 threads = 4 warps (2M x 2N), warp tile 64x64.
// BK=32 fp16, 3-stage cp.async pipeline, 80-byte padded rows.
#define RSH     40                        // row stride in halves (80 bytes)
#define STG     3
#define CHUNK_H (128 * RSH)               // halves per tile per stage
#define CHUNK_B (CHUNK_H * 2)             // bytes per tile per stage (10240)
#define DYNSM   (STG * CHUNK_B * 2)       // A + B rings = 61440 bytes

template<int MODE>
__global__ __launch_bounds__(128, 3) void k_ffgemm(
    const __half* __restrict__ A,  const __half* __restrict__ Bm,
    const float* __restrict__ bias, const float* __restrict__ src,
    float* __restrict__ outf, __half* __restrict__ outh)
{
    constexpr int KK   = (MODE == 0) ? DM : (MODE == 1) ? DFF : KEMB;
    constexpr int NKB  = KK / 32;
    constexpr int ASTR = KK;
    constexpr int OSTR = (MODE == 0) ? DFF : DM;

    extern __shared__ __half dynh[];
    __half* pA = dynh;                     // [STG][128][RSH]
    __half* pB = dynh + STG * CHUNK_H;

    const int tid  = threadIdx.x;
    const int lane = tid & 31;
    const int w    = tid >> 5;
    const int wm   = w & 1;      // 0..1  (M)
    const int wn   = w >> 1;     // 0..1  (N)
    const int m0   = blockIdx.y * 128;
    const int n0   = blockIdx.x * 128;
    const int g    = lane >> 2;  // 0..7
    const int tg   = lane & 3;   // 0..3

    const uint32_t baseA = smem_u32(pA);
    const uint32_t baseB = smem_u32(pB);

    // ldmatrix per-lane offsets (bytes) within a chunk tile
    const int lr = lane & 7;
    const int b3 = (lane >> 3) & 1;
    const int b4 = (lane >> 4) & 1;
    uint32_t offA[4], offB[4];
    #pragma unroll
    for (int mt = 0; mt < 4; mt++) {
        int row = wm * 64 + mt * 16 + lr + b3 * 8;
        offA[mt] = (uint32_t)(row * (RSH * 2) + b4 * 16);
    }
    #pragma unroll
    for (int ntp = 0; ntp < 4; ntp++) {
        int row = wn * 64 + ntp * 16 + lr + b4 * 8;
        offB[ntp] = (uint32_t)(row * (RSH * 2) + b3 * 16);
    }

    float acc[4][8][4];
    #pragma unroll
    for (int mt = 0; mt < 4; mt++)
        #pragma unroll
        for (int nt = 0; nt < 8; nt++)
            #pragma unroll
            for (int i = 0; i < 4; i++) acc[mt][nt][i] = 0.0f;

    const int srow = tid >> 2, skq = tid & 3;

    auto issue = [&](int kb, int s) {
        uint32_t dA = baseA + (uint32_t)s * CHUNK_B;
        uint32_t dB = baseB + (uint32_t)s * CHUNK_B;
        #pragma unroll
        for (int it = 0; it < 4; it++) {
            int row = it * 32 + srow;
            int kg  = kb * 32 + skq * 8;   // halves
            cp16(dA + row * (RSH * 2) + skq * 16, &A [(size_t)(m0 + row) * ASTR + kg]);
            cp16(dB + row * (RSH * 2) + skq * 16, &Bm[(size_t)(n0 + row) * ASTR + kg]);
        }
    };

    auto compute = [&](int s) {
        uint32_t cA = baseA + (uint32_t)s * CHUNK_B;
        uint32_t cB = baseB + (uint32_t)s * CHUNK_B;
        #pragma unroll
        for (int p = 0; p < 2; p++) {
            uint32_t af[4][4];
            #pragma unroll
            for (int mt = 0; mt < 4; mt++)
                ldsm4(af[mt][0], af[mt][1], af[mt][2], af[mt][3],
                      cA + offA[mt] + p * 32);
            uint32_t bf[8][2];
            #pragma unroll
            for (int ntp = 0; ntp < 4; ntp++)
                ldsm4(bf[2 * ntp][0], bf[2 * ntp][1],
                      bf[2 * ntp + 1][0], bf[2 * ntp + 1][1],
                      cB + offB[ntp] + p * 32);
            #pragma unroll
            for (int mt = 0; mt < 4; mt++)
                #pragma unroll
                for (int nt = 0; nt < 8; nt++)
                    mma16(acc[mt][nt], af[mt][0], af[mt][1], af[mt][2], af[mt][3],
                          bf[nt][0], bf[nt][1]);
        }
    };

    issue(0, 0); CP_COMMIT();
    issue(1, 1); CP_COMMIT();

    #pragma unroll 1
    for (int kb = 0; kb < NKB; kb++) {
        CP_WAIT1();                 // group kb complete (only kb+1 may be pending)
        __syncthreads();            // data visible; stage (kb+2)%3 free to refill
        if (kb + 2 < NKB) issue(kb + 2, (kb + 2) % 3);
        CP_COMMIT();
        compute(kb % 3);
    }

    // ---- epilogue
    const int whichv = (MODE == 2) ? (n0 >> 8) : 0;
    float* outfp = (MODE == 2) ? (outf + (size_t)whichv * EMB_M * DM) : outf;
    const int ncorr = (MODE == 2) ? whichv * 256 : 0;

    #pragma unroll
    for (int mt = 0; mt < 4; mt++) {
        int r0 = m0 + wm * 64 + mt * 16 + g;
        int r1 = r0 + 8;
        #pragma unroll
        for (int nt = 0; nt < 8; nt++) {
            int cb = n0 + wn * 64 + nt * 8 + tg * 2;
            float* c = acc[mt][nt];
            float2 bi = *(const float2*)&bias[cb];
            if (MODE == 0) {
                __half2 h0 = __floats2half2_rn(gelu_exact(c[0] + bi.x),
                                               gelu_exact(c[1] + bi.y));
                __half2 h1 = __floats2half2_rn(gelu_exact(c[2] + bi.x),
                                               gelu_exact(c[3] + bi.y));
                *(__half2*)&outh[(size_t)r0 * OSTR + cb] = h0;
                *(__half2*)&outh[(size_t)r1 * OSTR + cb] = h1;
            } else if (MODE == 1) {
                float2 al = *(const float2*)&g_al[cb];
                float2 bt = *(const float2*)&g_bt[cb];
                float2 s0 = *(const float2*)&src[(size_t)r0 * DM + cb];
                float2 s1 = *(const float2*)&src[(size_t)r1 * DM + cb];
                float2 o0 = make_float2(c[0] + bi.x + s0.x * al.x + bt.x,
                                        c[1] + bi.y + s0.y * al.y + bt.y);
                float2 o1 = make_float2(c[2] + bi.x + s1.x * al.x + bt.x,
                                        c[3] + bi.y + s1.y * al.y + bt.y);
                *(float2*)&outf[(size_t)r0 * OSTR + cb] = o0;
                *(float2*)&outf[(size_t)r1 * OSTR + cb] = o1;
            } else {
                int cl = cb - ncorr;
                float2 o0 = make_float2(c[0] + bi.x, c[1] + bi.y);
                float2 o1 = make_float2(c[2] + bi.x, c[3] + bi.y);
                *(float2*)&outfp[(size_t)r0 * OSTR + cl] = o0;
                *(float2*)&outfp[(size_t)r1 * OSTR + cl] = o1;
            }
        }
    }
}

// ---------------------------------------------------------------- launch
extern "C" void kernel_launch(void* const* d_in, const int* in_sizes, int n_in,
                              void* d_out, int out_size)
{
    const float* x_re   = (const float*)d_in[0];
    const float* x_im   = (const float*)d_in[1];
    const float* embWre = (const float*)d_in[2];
    const float* embWim = (const float*)d_in[3];
    const float* embbre = (const float*)d_in[4];
    const float* embbim = (const float*)d_in[5];
    const float* W1     = (const float*)d_in[6];
    const float* b1     = (const float*)d_in[7];
    const float* W2     = (const float*)d_in[8];
    const float* b2     = (const float*)d_in[9];
    const float* gamma1 = (const float*)d_in[10];
    const float* beta1  = (const float*)d_in[11];
    const float* gamma2 = (const float*)d_in[12];
    const float* beta2  = (const float*)d_in[13];
    float* out = (float*)d_out;

    float*  act  = nullptr; float*  src = nullptr; __half* srch = nullptr;
    __half* ffh  = nullptr; float*  P   = nullptr;
    __half* w1h  = nullptr; float*  b1m = nullptr; __half* w2h  = nullptr;
    __half* wEh  = nullptr; float*  bE  = nullptr;
    cudaGetSymbolAddress((void**)&act,  g_act);
    cudaGetSymbolAddress((void**)&src,  g_src);
    cudaGetSymbolAddress((void**)&srch, g_srch);
    cudaGetSymbolAddress((void**)&ffh,  g_ffh);
    cudaGetSymbolAddress((void**)&P,    g_P);
    cudaGetSymbolAddress((void**)&w1h,  g_w1h);
    cudaGetSymbolAddress((void**)&b1m,  g_b1m);
    cudaGetSymbolAddress((void**)&w2h,  g_w2h);
    cudaGetSymbolAddress((void**)&wEh,  g_wEh);
    cudaGetSymbolAddress((void**)&bE,   g_bE);

    cudaFuncSetAttribute(k_ffgemm<0>, cudaFuncAttributeMaxDynamicSharedMemorySize, DYNSM);
    cudaFuncSetAttribute(k_ffgemm<1>, cudaFuncAttributeMaxDynamicSharedMemorySize, DYNSM);
    cudaFuncSetAttribute(k_ffgemm<2>, cudaFuncAttributeMaxDynamicSharedMemorySize, DYNSM);

    k_init_affine<<<1, DM>>>();
    k_roundW2<<<(NL * DM * DFF) / 256, 256>>>(W2);

    // embed: pack fp16 operands, then fp16 GEMM
    __half* Ah = (__half*)P;   // reuse g_P (embed runs before any attn)
    {
        size_t na = (size_t)EMB_M * KEMB;
        k_packA<<<(int)((na + 255) / 256), 256>>>(x_re, x_im, Ah);
        size_t nb = (size_t)512 * KEMB;
        k_packW<<<(int)((nb + 255) / 256), 256>>>(embWre, embWim);
        k_packBias<<<1, 512>>>(embbre, embbim);
        dim3 ge(512 / 128, EMB_M / 128);
        k_ffgemm<2><<<ge, 128, DYNSM>>>(Ah, wEh, bE, nullptr, act, nullptr);
    }

    for (int l = 0; l < NL; l++) {
        const float* W1l = W1 + (size_t)l * DFF * DM;
        const float* b1l = b1 + (size_t)l * DFF;
        const float* b2l = b2 + (size_t)l * DM;
        __half* w2hl = w2h + (size_t)l * DM * DFF;

        {
            dim3 ga((CC + 31) / 32, DM / 32, BB);
            k_attn<<<ga, 256>>>(act, src, srch);
        }

        k_stats<<<NSTATB, DM>>>(src);
        k_finalize<<<1, DM>>>(gamma1 + l * DM, beta1 + l * DM);
        k_fold<<<DFF, DM>>>(W1l, b1l);

        {
            dim3 g1(DFF / 128, MROWS / 128);
            k_ffgemm<0><<<g1, 128, DYNSM>>>(srch, w1h, b1m, nullptr, nullptr, ffh);
            dim3 g2(DM / 128, MROWS / 128);
            k_ffgemm<1><<<g2, 128, DYNSM>>>(ffh, w2hl, b2l, src, act, nullptr);
        }

        k_stats<<<NSTATB, DM>>>(act);
        k_finalize<<<1, DM>>>(gamma2 + l * DM, beta2 + l * DM);
    }

    const size_t NO = (size_t)BB * CC * DM;
    k_out<<<(int)((NO + 255) / 256), 256>>>(act, out);
}